// round 1
// baseline (speedup 1.0000x reference)
#include <cuda_runtime.h>
#include <cuda_bf16.h>
#include <math.h>

// Problem constants
#define BB 4
#define TT 2048
#define DD 1024
#define HH 16
#define HS 64
#define MROWS (BB*TT)          // 8192
#define D3 (3*DD)              // 3072
#define D4 (4*DD)              // 4096

// ---------------- scratch (device globals; no allocs allowed) ----------------
__device__ float g_h  [MROWS*DD];     // LN1 output
__device__ float g_qkv[MROWS*D3];     // fused QKV, layout [b*T+t][ q(h,k) | k(h,k) | v(h,k) ]
__device__ float g_Wt [DD*D3];        // repacked [D, 3D] weight (col = sec*1024 + h*64 + k)
__device__ float g_o  [MROWS*DD];     // attention output, heads concatenated
__device__ float g_x2 [MROWS*DD];     // h + proj
__device__ float g_h2 [MROWS*DD];     // LN2 output
__device__ float g_mid[MROWS*D4];     // FFN hidden

// ---------------- weight repack: Wq/Wk/Wv [H,D,HS] -> Wt [D, 3D] -------------
__global__ void prep_w_kernel(const float* __restrict__ Wq,
                              const float* __restrict__ Wk,
                              const float* __restrict__ Wv,
                              float* __restrict__ Wt) {
    int idx = blockIdx.x * 256 + threadIdx.x;        // over D*3D
    int d = idx / D3;
    int c = idx - d * D3;
    int sec = c >> 10;           // 0=q,1=k,2=v
    int cc  = c & 1023;
    int hh  = cc >> 6;
    int kk  = cc & 63;
    const float* W = (sec == 0) ? Wq : (sec == 1) ? Wk : Wv;
    Wt[idx] = W[(size_t)hh * (DD * HS) + (size_t)d * HS + kk];
}

// ---------------- LayerNorm: one block per row of 1024 -----------------------
__global__ void ln_kernel(const float* __restrict__ x,
                          const float* __restrict__ g,
                          const float* __restrict__ b,
                          float* __restrict__ y) {
    int row = blockIdx.x;
    int tid = threadIdx.x;                 // 256 threads
    const float4 v = *(const float4*)(x + (size_t)row * DD + tid * 4);
    float s  = v.x + v.y + v.z + v.w;
    float sq = v.x*v.x + v.y*v.y + v.z*v.z + v.w*v.w;
    // warp reduce
    #pragma unroll
    for (int o = 16; o > 0; o >>= 1) {
        s  += __shfl_xor_sync(0xffffffffu, s,  o);
        sq += __shfl_xor_sync(0xffffffffu, sq, o);
    }
    __shared__ float ws[8], wq[8];
    int wid = tid >> 5, lid = tid & 31;
    if (lid == 0) { ws[wid] = s; wq[wid] = sq; }
    __syncthreads();
    if (wid == 0) {
        float a = (lid < 8) ? ws[lid] : 0.f;
        float c = (lid < 8) ? wq[lid] : 0.f;
        #pragma unroll
        for (int o = 4; o > 0; o >>= 1) {
            a += __shfl_xor_sync(0xffffffffu, a, o);
            c += __shfl_xor_sync(0xffffffffu, c, o);
        }
        if (lid == 0) { ws[0] = a; wq[0] = c; }
    }
    __syncthreads();
    float mu  = ws[0] * (1.0f / DD);
    float var = wq[0] * (1.0f / DD) - mu * mu;
    float inv = rsqrtf(var + 1e-5f);
    const float4 gg = *(const float4*)(g + tid * 4);
    const float4 bb = *(const float4*)(b + tid * 4);
    float4 o4;
    o4.x = (v.x - mu) * inv * gg.x + bb.x;
    o4.y = (v.y - mu) * inv * gg.y + bb.y;
    o4.z = (v.z - mu) * inv * gg.z + bb.z;
    o4.w = (v.w - mu) * inv * gg.w + bb.w;
    *(float4*)(y + (size_t)row * DD + tid * 4) = o4;
}

// ---------------- GEMM: C[M,N] = A[M,K] @ B[K,N] (+bias)(+relu)(+res) --------
// 128x128 tile, BK=16, 256 threads, 8x8 micro-tile. All dims divisible.
template <bool RELU>
__global__ __launch_bounds__(256)
void gemm_kernel(const float* __restrict__ A, const float* __restrict__ B,
                 const float* __restrict__ bias, const float* __restrict__ res,
                 float* __restrict__ C, int M, int N, int K) {
    __shared__ float As[16][132];   // A^T tile (k-major), padded
    __shared__ float Bs[16][128];
    int t  = threadIdx.x;
    int tx = t & 15, ty = t >> 4;
    int bn = blockIdx.x, bm = blockIdx.y;
    const int arow0 = bm * 128;
    const int bcol0 = bn * 128;

    float acc[8][8];
    #pragma unroll
    for (int i = 0; i < 8; i++)
        #pragma unroll
        for (int j = 0; j < 8; j++) acc[i][j] = 0.f;

    for (int k0 = 0; k0 < K; k0 += 16) {
        // load A tile (128x16) -> As transposed
        #pragma unroll
        for (int i = 0; i < 2; i++) {
            int idx = t + i * 256;          // 0..511
            int row = idx >> 2;
            int kc  = (idx & 3) * 4;
            float4 a4 = *(const float4*)(A + (size_t)(arow0 + row) * K + k0 + kc);
            As[kc + 0][row] = a4.x;
            As[kc + 1][row] = a4.y;
            As[kc + 2][row] = a4.z;
            As[kc + 3][row] = a4.w;
        }
        // load B tile (16x128)
        #pragma unroll
        for (int i = 0; i < 2; i++) {
            int idx = t + i * 256;
            int kr  = idx >> 5;
            int col = (idx & 31) * 4;
            *(float4*)(&Bs[kr][col]) =
                *(const float4*)(B + (size_t)(k0 + kr) * N + bcol0 + col);
        }
        __syncthreads();
        #pragma unroll
        for (int kk = 0; kk < 16; kk++) {
            float4 a0 = *(const float4*)(&As[kk][ty * 8]);
            float4 a1 = *(const float4*)(&As[kk][ty * 8 + 4]);
            float4 b0 = *(const float4*)(&Bs[kk][tx * 8]);
            float4 b1 = *(const float4*)(&Bs[kk][tx * 8 + 4]);
            float ar[8] = {a0.x, a0.y, a0.z, a0.w, a1.x, a1.y, a1.z, a1.w};
            float br[8] = {b0.x, b0.y, b0.z, b0.w, b1.x, b1.y, b1.z, b1.w};
            #pragma unroll
            for (int i = 0; i < 8; i++)
                #pragma unroll
                for (int j = 0; j < 8; j++)
                    acc[i][j] += ar[i] * br[j];
        }
        __syncthreads();
    }
    // epilogue
    #pragma unroll
    for (int i = 0; i < 8; i++) {
        int row = arow0 + ty * 8 + i;
        #pragma unroll
        for (int j = 0; j < 8; j++) {
            int col = bcol0 + tx * 8 + j;
            float v = acc[i][j];
            if (bias) v += bias[col];
            if (RELU) v = fmaxf(v, 0.f);
            if (res)  v += res[(size_t)row * N + col];
            C[(size_t)row * N + col] = v;
        }
    }
}

// ---------------- Causal flash attention ------------------------------------
// grid: (T/64, B*H); block: 64 threads; thread r handles one query row fully.
// qkv layout per row: [ q(h*64+k) | 1024 + k(h*64+k) | 2048 + v(h*64+k) ]
#define ATTN_SMEM_FLOATS (64*68*2 + 64*65)
__global__ __launch_bounds__(64)
void attn_kernel(const float* __restrict__ qkv, float* __restrict__ o) {
    extern __shared__ float smem[];
    float* Ks = smem;                 // [64][68]
    float* Vs = smem + 64 * 68;       // [64][68]
    float* Ss = smem + 64 * 68 * 2;   // [64][65]

    int tid = threadIdx.x;
    int bq  = blockIdx.x;                 // query tile
    int b   = blockIdx.y >> 4;
    int h   = blockIdx.y & 15;
    int r   = bq * 64 + tid;              // query row within seq
    size_t grow = (size_t)b * TT + r;

    const float scale = 0.03125f;         // D^-0.5 = 1/32
    float q[64];
    {
        const float4* q4 = (const float4*)(qkv + grow * D3 + h * 64);
        #pragma unroll
        for (int i = 0; i < 16; i++) {
            float4 v = q4[i];
            q[4*i+0] = v.x * scale; q[4*i+1] = v.y * scale;
            q[4*i+2] = v.z * scale; q[4*i+3] = v.w * scale;
        }
    }
    float acc[64];
    #pragma unroll
    for (int d = 0; d < 64; d++) acc[d] = 0.f;
    float m = -1e30f, l = 0.f;

    for (int kt = 0; kt <= bq; kt++) {
        int kb = kt * 64;
        // cooperative K/V tile load: thread tid loads key row kb+tid
        {
            const float* krow = qkv + ((size_t)b * TT + kb + tid) * D3 + DD   + h * 64;
            const float* vrow = qkv + ((size_t)b * TT + kb + tid) * D3 + 2*DD + h * 64;
            #pragma unroll
            for (int i = 0; i < 16; i++) {
                *(float4*)(Ks + tid * 68 + i * 4) = *(const float4*)(krow + i * 4);
                *(float4*)(Vs + tid * 68 + i * 4) = *(const float4*)(vrow + i * 4);
            }
        }
        __syncthreads();
        int jmax = (kt == bq) ? tid : 63;     // causal bound
        float mt = -1e30f;
        for (int j = 0; j <= jmax; j++) {
            const float* kj = Ks + j * 68;
            float s0 = 0.f, s1 = 0.f, s2 = 0.f, s3 = 0.f;
            #pragma unroll
            for (int d = 0; d < 64; d += 4) {
                s0 += q[d+0] * kj[d+0];
                s1 += q[d+1] * kj[d+1];
                s2 += q[d+2] * kj[d+2];
                s3 += q[d+3] * kj[d+3];
            }
            float s = (s0 + s1) + (s2 + s3);
            Ss[tid * 65 + j] = s;
            mt = fmaxf(mt, s);
        }
        float mn = fmaxf(m, mt);
        float sc = __expf(m - mn);
        l *= sc;
        #pragma unroll
        for (int d = 0; d < 64; d++) acc[d] *= sc;
        for (int j = 0; j <= jmax; j++) {
            float p = __expf(Ss[tid * 65 + j] - mn);
            l += p;
            const float* vj = Vs + j * 68;
            #pragma unroll
            for (int d = 0; d < 64; d++) acc[d] += p * vj[d];
        }
        m = mn;
        __syncthreads();
    }
    float rl = 1.0f / l;
    float* orow = o + grow * DD + h * 64;
    #pragma unroll
    for (int i = 0; i < 16; i++) {
        float4 v;
        v.x = acc[4*i+0] * rl; v.y = acc[4*i+1] * rl;
        v.z = acc[4*i+2] * rl; v.w = acc[4*i+3] * rl;
        *(float4*)(orow + i * 4) = v;
    }
}

// ---------------- launch ------------------------------------------------------
extern "C" void kernel_launch(void* const* d_in, const int* in_sizes, int n_in,
                              void* d_out, int out_size) {
    const float* x   = (const float*)d_in[0];
    const float* Wq  = (const float*)d_in[1];
    const float* Wk  = (const float*)d_in[2];
    const float* Wv  = (const float*)d_in[3];
    const float* Wp  = (const float*)d_in[4];
    const float* bp  = (const float*)d_in[5];
    const float* W1  = (const float*)d_in[6];
    const float* b1  = (const float*)d_in[7];
    const float* W2  = (const float*)d_in[8];
    const float* b2  = (const float*)d_in[9];
    const float* g1  = (const float*)d_in[10];
    const float* be1 = (const float*)d_in[11];
    const float* g2  = (const float*)d_in[12];
    const float* be2 = (const float*)d_in[13];
    float* out = (float*)d_out;

    float *h, *qkv, *Wt, *o, *x2, *h2, *mid;
    cudaGetSymbolAddress((void**)&h,   g_h);
    cudaGetSymbolAddress((void**)&qkv, g_qkv);
    cudaGetSymbolAddress((void**)&Wt,  g_Wt);
    cudaGetSymbolAddress((void**)&o,   g_o);
    cudaGetSymbolAddress((void**)&x2,  g_x2);
    cudaGetSymbolAddress((void**)&h2,  g_h2);
    cudaGetSymbolAddress((void**)&mid, g_mid);

    const int attn_smem = ATTN_SMEM_FLOATS * (int)sizeof(float);
    cudaFuncSetAttribute(attn_kernel,
                         cudaFuncAttributeMaxDynamicSharedMemorySize, attn_smem);

    // 1) repack QKV weights into [D, 3D]
    prep_w_kernel<<<(DD * D3) / 256, 256>>>(Wq, Wk, Wv, Wt);
    // 2) LN1: x -> h
    ln_kernel<<<MROWS, 256>>>(x, g1, be1, h);
    // 3) QKV GEMM: [8192,1024] @ [1024,3072]
    gemm_kernel<false><<<dim3(D3 / 128, MROWS / 128), 256>>>(
        h, Wt, nullptr, nullptr, qkv, MROWS, D3, DD);
    // 4) causal attention
    attn_kernel<<<dim3(TT / 64, BB * HH), 64, attn_smem>>>(qkv, o);
    // 5) proj GEMM + bias + residual(h) -> x2
    gemm_kernel<false><<<dim3(DD / 128, MROWS / 128), 256>>>(
        o, Wp, bp, h, x2, MROWS, DD, DD);
    // 6) LN2: x2 -> h2
    ln_kernel<<<MROWS, 256>>>(x2, g2, be2, h2);
    // 7) FFN1 GEMM + bias + relu -> mid
    gemm_kernel<true><<<dim3(D4 / 128, MROWS / 128), 256>>>(
        h2, W1, b1, nullptr, mid, MROWS, D4, DD);
    // 8) FFN2 GEMM + bias + residual(h2) -> out
    gemm_kernel<false><<<dim3(DD / 128, MROWS / 128), 256>>>(
        mid, W2, b2, h2, out, MROWS, DD, D4);
}

// round 3
// speedup vs baseline: 1.6610x; 1.6610x over previous
#include <cuda_runtime.h>
#include <cuda_bf16.h>
#include <cstdint>
#include <math.h>

// Problem constants
#define BB 4
#define TT 2048
#define DD 1024
#define HH 16
#define HS 64
#define MROWS (BB*TT)          // 8192
#define D3 (3*DD)              // 3072
#define D4 (4*DD)              // 4096

// ---------------- scratch (device globals; no allocs allowed) ----------------
__device__ float g_h  [MROWS*DD];     // LN1 output
__device__ float g_qkv[MROWS*D3];     // fused QKV
__device__ float g_o  [MROWS*DD];     // attention output
__device__ float g_x2 [MROWS*DD];     // h + proj
__device__ float g_h2 [MROWS*DD];     // LN2 output
__device__ float g_mid[MROWS*D4];     // FFN hidden
// bf16 hi/lo weights, [N][K] layout
__device__ __nv_bfloat16 g_Wqkv_h[D3*DD], g_Wqkv_l[D3*DD];
__device__ __nv_bfloat16 g_Wp_h [DD*DD], g_Wp_l [DD*DD];
__device__ __nv_bfloat16 g_W1_h [D4*DD], g_W1_l [D4*DD];
__device__ __nv_bfloat16 g_W2_h [DD*D4], g_W2_l [DD*D4];

// ======================= small PTX helpers ===================================
__device__ __forceinline__ uint32_t smem_u32(const void* p) {
    uint32_t a;
    asm("{ .reg .u64 t; cvta.to.shared.u64 t, %1; cvt.u32.u64 %0, t; }" : "=r"(a) : "l"(p));
    return a;
}
__device__ __forceinline__ void ldm4(uint32_t* r, uint32_t addr) {
    asm volatile("ldmatrix.sync.aligned.m8n8.x4.shared.b16 {%0,%1,%2,%3}, [%4];"
        : "=r"(r[0]), "=r"(r[1]), "=r"(r[2]), "=r"(r[3]) : "r"(addr));
}
__device__ __forceinline__ void mma16816(float* d, const uint32_t* a, const uint32_t* b) {
    asm volatile("mma.sync.aligned.m16n8k16.row.col.f32.bf16.bf16.f32 "
        "{%0,%1,%2,%3}, {%4,%5,%6,%7}, {%8,%9}, {%0,%1,%2,%3};"
        : "+f"(d[0]), "+f"(d[1]), "+f"(d[2]), "+f"(d[3])
        : "r"(a[0]), "r"(a[1]), "r"(a[2]), "r"(a[3]), "r"(b[0]), "r"(b[1]));
}
__device__ __forceinline__ uint32_t pack_bf16(float a, float b) {
    __nv_bfloat16 x = __float2bfloat16(a), y = __float2bfloat16(b);
    return ((uint32_t)__bfloat16_as_ushort(y) << 16) | __bfloat16_as_ushort(x);
}

// ======== weight prep: transpose W[K][N] -> out[N][K] bf16 hi/lo =============
__global__ void prep_tr(const float* __restrict__ W,
                        __nv_bfloat16* __restrict__ oh,
                        __nv_bfloat16* __restrict__ ol, int K, int N) {
    __shared__ float ts[32][33];
    int n0 = blockIdx.x * 32, k0 = blockIdx.y * 32;
    int tx = threadIdx.x, ty = threadIdx.y;     // (32,8)
    #pragma unroll
    for (int i = 0; i < 4; i++)
        ts[ty + 8*i][tx] = W[(size_t)(k0 + ty + 8*i) * N + n0 + tx];
    __syncthreads();
    #pragma unroll
    for (int i = 0; i < 4; i++) {
        float v = ts[tx][ty + 8*i];
        size_t o = (size_t)(n0 + ty + 8*i) * K + k0 + tx;
        __nv_bfloat16 h = __float2bfloat16(v);
        oh[o] = h;
        ol[o] = __float2bfloat16(v - __bfloat162float(h));
    }
}

// QKV weights: Wq/Wk/Wv [H][D][HS] -> out[n=(sec,h,hs)][k=d] bf16 hi/lo
__global__ void prep_qkv(const float* __restrict__ Wq, const float* __restrict__ Wk,
                         const float* __restrict__ Wv,
                         __nv_bfloat16* __restrict__ oh, __nv_bfloat16* __restrict__ ol) {
    __shared__ float ts[32][33];
    int hs0 = blockIdx.x * 32;
    int d0  = blockIdx.y * 32;
    int z   = blockIdx.z;
    int sec = z >> 4, hh = z & 15;
    const float* W = (sec == 0) ? Wq : (sec == 1) ? Wk : Wv;
    int tx = threadIdx.x, ty = threadIdx.y;
    #pragma unroll
    for (int i = 0; i < 4; i++)
        ts[ty + 8*i][tx] = W[(size_t)hh * (DD*HS) + (size_t)(d0 + ty + 8*i) * HS + hs0 + tx];
    __syncthreads();
    #pragma unroll
    for (int i = 0; i < 4; i++) {
        float v = ts[tx][ty + 8*i];
        int n = sec * 1024 + hh * 64 + hs0 + ty + 8*i;
        size_t o = (size_t)n * DD + d0 + tx;
        __nv_bfloat16 h = __float2bfloat16(v);
        oh[o] = h;
        ol[o] = __float2bfloat16(v - __bfloat162float(h));
    }
}

// ---------------- LayerNorm -------------------------------------------------
__global__ void ln_kernel(const float* __restrict__ x,
                          const float* __restrict__ g,
                          const float* __restrict__ b,
                          float* __restrict__ y) {
    int row = blockIdx.x;
    int tid = threadIdx.x;
    const float4 v = *(const float4*)(x + (size_t)row * DD + tid * 4);
    float s  = v.x + v.y + v.z + v.w;
    float sq = v.x*v.x + v.y*v.y + v.z*v.z + v.w*v.w;
    #pragma unroll
    for (int o = 16; o > 0; o >>= 1) {
        s  += __shfl_xor_sync(0xffffffffu, s,  o);
        sq += __shfl_xor_sync(0xffffffffu, sq, o);
    }
    __shared__ float ws[8], wq[8];
    int wid = tid >> 5, lid = tid & 31;
    if (lid == 0) { ws[wid] = s; wq[wid] = sq; }
    __syncthreads();
    if (wid == 0) {
        float a = (lid < 8) ? ws[lid] : 0.f;
        float c = (lid < 8) ? wq[lid] : 0.f;
        #pragma unroll
        for (int o = 4; o > 0; o >>= 1) {
            a += __shfl_xor_sync(0xffffffffu, a, o);
            c += __shfl_xor_sync(0xffffffffu, c, o);
        }
        if (lid == 0) { ws[0] = a; wq[0] = c; }
    }
    __syncthreads();
    float mu  = ws[0] * (1.0f / DD);
    float var = wq[0] * (1.0f / DD) - mu * mu;
    float inv = rsqrtf(var + 1e-5f);
    const float4 gg = *(const float4*)(g + tid * 4);
    const float4 bb = *(const float4*)(b + tid * 4);
    float4 o4;
    o4.x = (v.x - mu) * inv * gg.x + bb.x;
    o4.y = (v.y - mu) * inv * gg.y + bb.y;
    o4.z = (v.z - mu) * inv * gg.z + bb.z;
    o4.w = (v.w - mu) * inv * gg.w + bb.w;
    *(float4*)(y + (size_t)row * DD + tid * 4) = o4;
}

// ============ mma.sync GEMM: C[M,N] = A[M,K] @ Wt[N,K]^T =====================
// split-bf16, fp32 accum: D += Ah*Bh + Al*Bh + Ah*Bl
// CTA 128x128, 8 warps (4Mx2N), warp tile 32x64, K-chunk 32, double-buffered.
#define LDT 40                         // smem row stride in bf16 elements (80B)
#define TILE_BYTES (128*LDT*2)         // 10240
#define STAGE_BYTES (4*TILE_BYTES)     // Ah, Al, Bh, Bl = 40960
#define GEMM_SMEM (2*STAGE_BYTES)      // 81920

template <bool RELU>
__global__ __launch_bounds__(256)
void gemm_tc(const float* __restrict__ A,
             const __nv_bfloat16* __restrict__ Bh, const __nv_bfloat16* __restrict__ Bl,
             const float* __restrict__ bias, const float* __restrict__ res,
             float* __restrict__ C, int M, int N, int K) {
    extern __shared__ char smem[];
    uint32_t sb = smem_u32(smem);
    int tid = threadIdx.x, wid = tid >> 5, lane = tid & 31;
    int wm = wid >> 1, wn = wid & 1;
    int m0 = blockIdx.y * 128, n0 = blockIdx.x * 128;

    // gmem load coordinates: 2 threads per row
    int lr   = tid >> 1;            // row 0..127
    int lseg = (tid & 1) * 16;      // col segment 0 or 16

    const float* Ap0 = A + (size_t)(m0 + lr) * K + lseg;
    const __nv_bfloat16* Bhp0 = Bh + (size_t)(n0 + lr) * K + lseg;
    const __nv_bfloat16* Blp0 = Bl + (size_t)(n0 + lr) * K + lseg;

    float acc[2][8][4];
    #pragma unroll
    for (int i = 0; i < 2; i++)
        #pragma unroll
        for (int j = 0; j < 8; j++)
            #pragma unroll
            for (int q = 0; q < 4; q++) acc[i][j][q] = 0.f;

    const int nch = K >> 5;

    float4 pa[4];
    uint4  pbh[2], pbl[2];

    // ---- prologue: load chunk 0 ----
    #pragma unroll
    for (int i = 0; i < 4; i++) pa[i] = *(const float4*)(Ap0 + i * 4);
    #pragma unroll
    for (int i = 0; i < 2; i++) {
        pbh[i] = *(const uint4*)(Bhp0 + i * 8);
        pbl[i] = *(const uint4*)(Blp0 + i * 8);
    }
    {   // store chunk 0 into stage 0
        char* st = smem;
        uint32_t ro = (uint32_t)(lr * LDT + lseg) * 2;
        #pragma unroll
        for (int i = 0; i < 4; i++) {
            float4 v = pa[i];
            __nv_bfloat16 h0 = __float2bfloat16(v.x), h1 = __float2bfloat16(v.y);
            __nv_bfloat16 h2 = __float2bfloat16(v.z), h3 = __float2bfloat16(v.w);
            uint2 hp, lp;
            hp.x = ((uint32_t)__bfloat16_as_ushort(h1) << 16) | __bfloat16_as_ushort(h0);
            hp.y = ((uint32_t)__bfloat16_as_ushort(h3) << 16) | __bfloat16_as_ushort(h2);
            lp.x = pack_bf16(v.x - __bfloat162float(h0), v.y - __bfloat162float(h1));
            lp.y = pack_bf16(v.z - __bfloat162float(h2), v.w - __bfloat162float(h3));
            *(uint2*)(st + 0*TILE_BYTES + ro + i * 8) = hp;
            *(uint2*)(st + 1*TILE_BYTES + ro + i * 8) = lp;
        }
        #pragma unroll
        for (int i = 0; i < 2; i++) {
            *(uint4*)(st + 2*TILE_BYTES + ro + i * 16) = pbh[i];
            *(uint4*)(st + 3*TILE_BYTES + ro + i * 16) = pbl[i];
        }
    }
    __syncthreads();

    // ldmatrix lane coordinates
    int a_r = (( lane >> 3) & 1) * 8 + (lane & 7);     // + mt*16 + wm*32
    int a_c = (lane >> 4) * 8;                          // + k16
    int b_r = (lane >> 4) * 8 + (lane & 7);            // + nt*16 + wn*64
    int b_c = ((lane >> 3) & 1) * 8;                    // + k16

    for (int c = 0; c < nch; c++) {
        // prefetch chunk c+1
        if (c + 1 < nch) {
            int off = (c + 1) * 32;
            #pragma unroll
            for (int i = 0; i < 4; i++) pa[i] = *(const float4*)(Ap0 + off + i * 4);
            #pragma unroll
            for (int i = 0; i < 2; i++) {
                pbh[i] = *(const uint4*)(Bhp0 + off + i * 8);
                pbl[i] = *(const uint4*)(Blp0 + off + i * 8);
            }
        }
        // compute on stage c&1
        uint32_t stage = sb + (uint32_t)(c & 1) * STAGE_BYTES;
        #pragma unroll
        for (int k16 = 0; k16 < 32; k16 += 16) {
            uint32_t ah[2][4], al[2][4];
            #pragma unroll
            for (int mt = 0; mt < 2; mt++) {
                uint32_t ao = (uint32_t)((wm*32 + mt*16 + a_r) * LDT + k16 + a_c) * 2;
                ldm4(ah[mt], stage + 0*TILE_BYTES + ao);
                ldm4(al[mt], stage + 1*TILE_BYTES + ao);
            }
            #pragma unroll
            for (int nt = 0; nt < 4; nt++) {
                uint32_t bh[4], bl[4];
                uint32_t bo = (uint32_t)((wn*64 + nt*16 + b_r) * LDT + k16 + b_c) * 2;
                ldm4(bh, stage + 2*TILE_BYTES + bo);
                ldm4(bl, stage + 3*TILE_BYTES + bo);
                #pragma unroll
                for (int mt = 0; mt < 2; mt++) {
                    mma16816(acc[mt][2*nt+0], ah[mt], bh + 0);
                    mma16816(acc[mt][2*nt+0], al[mt], bh + 0);
                    mma16816(acc[mt][2*nt+0], ah[mt], bl + 0);
                    mma16816(acc[mt][2*nt+1], ah[mt], bh + 2);
                    mma16816(acc[mt][2*nt+1], al[mt], bh + 2);
                    mma16816(acc[mt][2*nt+1], ah[mt], bl + 2);
                }
            }
        }
        // store chunk c+1 into stage (c+1)&1
        if (c + 1 < nch) {
            char* st = smem + ((c + 1) & 1) * STAGE_BYTES;
            uint32_t ro = (uint32_t)(lr * LDT + lseg) * 2;
            #pragma unroll
            for (int i = 0; i < 4; i++) {
                float4 v = pa[i];
                __nv_bfloat16 h0 = __float2bfloat16(v.x), h1 = __float2bfloat16(v.y);
                __nv_bfloat16 h2 = __float2bfloat16(v.z), h3 = __float2bfloat16(v.w);
                uint2 hp, lp;
                hp.x = ((uint32_t)__bfloat16_as_ushort(h1) << 16) | __bfloat16_as_ushort(h0);
                hp.y = ((uint32_t)__bfloat16_as_ushort(h3) << 16) | __bfloat16_as_ushort(h2);
                lp.x = pack_bf16(v.x - __bfloat162float(h0), v.y - __bfloat162float(h1));
                lp.y = pack_bf16(v.z - __bfloat162float(h2), v.w - __bfloat162float(h3));
                *(uint2*)(st + 0*TILE_BYTES + ro + i * 8) = hp;
                *(uint2*)(st + 1*TILE_BYTES + ro + i * 8) = lp;
            }
            #pragma unroll
            for (int i = 0; i < 2; i++) {
                *(uint4*)(st + 2*TILE_BYTES + ro + i * 16) = pbh[i];
                *(uint4*)(st + 3*TILE_BYTES + ro + i * 16) = pbl[i];
            }
        }
        __syncthreads();
    }

    // ---- epilogue ----
    int trow = lane >> 2, tcol = (lane & 3) * 2;
    #pragma unroll
    for (int mt = 0; mt < 2; mt++) {
        #pragma unroll
        for (int rr = 0; rr < 2; rr++) {
            int row = m0 + wm*32 + mt*16 + rr*8 + trow;
            #pragma unroll
            for (int j = 0; j < 8; j++) {
                int col = n0 + wn*64 + j*8 + tcol;
                float v0 = acc[mt][j][rr*2+0];
                float v1 = acc[mt][j][rr*2+1];
                if (bias) { v0 += bias[col]; v1 += bias[col+1]; }
                if (RELU) { v0 = fmaxf(v0, 0.f); v1 = fmaxf(v1, 0.f); }
                if (res) {
                    const float2 r2 = *(const float2*)(res + (size_t)row * N + col);
                    v0 += r2.x; v1 += r2.y;
                }
                float2 o2; o2.x = v0; o2.y = v1;
                *(float2*)(C + (size_t)row * N + col) = o2;
            }
        }
    }
}

// ---------------- Causal flash attention (unchanged) -------------------------
#define ATTN_SMEM_FLOATS (64*68*2 + 64*65)
__global__ __launch_bounds__(64)
void attn_kernel(const float* __restrict__ qkv, float* __restrict__ o) {
    extern __shared__ float smemf[];
    float* Ks = smemf;
    float* Vs = smemf + 64 * 68;
    float* Ss = smemf + 64 * 68 * 2;

    int tid = threadIdx.x;
    int bq  = blockIdx.x;
    int b   = blockIdx.y >> 4;
    int h   = blockIdx.y & 15;
    int r   = bq * 64 + tid;
    size_t grow = (size_t)b * TT + r;

    const float scale = 0.03125f;
    float q[64];
    {
        const float4* q4 = (const float4*)(qkv + grow * D3 + h * 64);
        #pragma unroll
        for (int i = 0; i < 16; i++) {
            float4 v = q4[i];
            q[4*i+0] = v.x * scale; q[4*i+1] = v.y * scale;
            q[4*i+2] = v.z * scale; q[4*i+3] = v.w * scale;
        }
    }
    float acc[64];
    #pragma unroll
    for (int d = 0; d < 64; d++) acc[d] = 0.f;
    float m = -1e30f, l = 0.f;

    for (int kt = 0; kt <= bq; kt++) {
        int kb = kt * 64;
        {
            const float* krow = qkv + ((size_t)b * TT + kb + tid) * D3 + DD   + h * 64;
            const float* vrow = qkv + ((size_t)b * TT + kb + tid) * D3 + 2*DD + h * 64;
            #pragma unroll
            for (int i = 0; i < 16; i++) {
                *(float4*)(Ks + tid * 68 + i * 4) = *(const float4*)(krow + i * 4);
                *(float4*)(Vs + tid * 68 + i * 4) = *(const float4*)(vrow + i * 4);
            }
        }
        __syncthreads();
        int jmax = (kt == bq) ? tid : 63;
        float mt = -1e30f;
        for (int j = 0; j <= jmax; j++) {
            const float* kj = Ks + j * 68;
            float s0 = 0.f, s1 = 0.f, s2 = 0.f, s3 = 0.f;
            #pragma unroll
            for (int d = 0; d < 64; d += 4) {
                s0 += q[d+0] * kj[d+0];
                s1 += q[d+1] * kj[d+1];
                s2 += q[d+2] * kj[d+2];
                s3 += q[d+3] * kj[d+3];
            }
            float s = (s0 + s1) + (s2 + s3);
            Ss[tid * 65 + j] = s;
            mt = fmaxf(mt, s);
        }
        float mn = fmaxf(m, mt);
        float sc = __expf(m - mn);
        l *= sc;
        #pragma unroll
        for (int d = 0; d < 64; d++) acc[d] *= sc;
        for (int j = 0; j <= jmax; j++) {
            float p = __expf(Ss[tid * 65 + j] - mn);
            l += p;
            const float* vj = Vs + j * 68;
            #pragma unroll
            for (int d = 0; d < 64; d++) acc[d] += p * vj[d];
        }
        m = mn;
        __syncthreads();
    }
    float rl = 1.0f / l;
    float* orow = o + grow * DD + h * 64;
    #pragma unroll
    for (int i = 0; i < 16; i++) {
        float4 v;
        v.x = acc[4*i+0] * rl; v.y = acc[4*i+1] * rl;
        v.z = acc[4*i+2] * rl; v.w = acc[4*i+3] * rl;
        *(float4*)(orow + i * 4) = v;
    }
}

// ---------------- launch ------------------------------------------------------
extern "C" void kernel_launch(void* const* d_in, const int* in_sizes, int n_in,
                              void* d_out, int out_size) {
    const float* x   = (const float*)d_in[0];
    const float* Wq  = (const float*)d_in[1];
    const float* Wk  = (const float*)d_in[2];
    const float* Wv  = (const float*)d_in[3];
    const float* Wp  = (const float*)d_in[4];
    const float* bp  = (const float*)d_in[5];
    const float* W1  = (const float*)d_in[6];
    const float* b1  = (const float*)d_in[7];
    const float* W2  = (const float*)d_in[8];
    const float* b2  = (const float*)d_in[9];
    const float* g1  = (const float*)d_in[10];
    const float* be1 = (const float*)d_in[11];
    const float* g2  = (const float*)d_in[12];
    const float* be2 = (const float*)d_in[13];
    float* out = (float*)d_out;

    float *h, *qkv, *o, *x2, *h2, *mid;
    cudaGetSymbolAddress((void**)&h,   g_h);
    cudaGetSymbolAddress((void**)&qkv, g_qkv);
    cudaGetSymbolAddress((void**)&o,   g_o);
    cudaGetSymbolAddress((void**)&x2,  g_x2);
    cudaGetSymbolAddress((void**)&h2,  g_h2);
    cudaGetSymbolAddress((void**)&mid, g_mid);
    __nv_bfloat16 *Wqkv_h, *Wqkv_l, *Wp_h, *Wp_l, *W1_h, *W1_l, *W2_h, *W2_l;
    cudaGetSymbolAddress((void**)&Wqkv_h, g_Wqkv_h);
    cudaGetSymbolAddress((void**)&Wqkv_l, g_Wqkv_l);
    cudaGetSymbolAddress((void**)&Wp_h, g_Wp_h);
    cudaGetSymbolAddress((void**)&Wp_l, g_Wp_l);
    cudaGetSymbolAddress((void**)&W1_h, g_W1_h);
    cudaGetSymbolAddress((void**)&W1_l, g_W1_l);
    cudaGetSymbolAddress((void**)&W2_h, g_W2_h);
    cudaGetSymbolAddress((void**)&W2_l, g_W2_l);

    const int attn_smem = ATTN_SMEM_FLOATS * (int)sizeof(float);
    cudaFuncSetAttribute(attn_kernel,
                         cudaFuncAttributeMaxDynamicSharedMemorySize, attn_smem);
    cudaFuncSetAttribute(gemm_tc<false>,
                         cudaFuncAttributeMaxDynamicSharedMemorySize, GEMM_SMEM);
    cudaFuncSetAttribute(gemm_tc<true>,
                         cudaFuncAttributeMaxDynamicSharedMemorySize, GEMM_SMEM);

    dim3 tb(32, 8);
    prep_qkv<<<dim3(2, 32, 48), tb>>>(Wq, Wk, Wv, Wqkv_h, Wqkv_l);
    prep_tr<<<dim3(DD/32, DD/32), tb>>>(Wp, Wp_h, Wp_l, DD, DD);
    prep_tr<<<dim3(D4/32, DD/32), tb>>>(W1, W1_h, W1_l, DD, D4);
    prep_tr<<<dim3(DD/32, D4/32), tb>>>(W2, W2_h, W2_l, D4, DD);

    // LN1
    ln_kernel<<<MROWS, 256>>>(x, g1, be1, h);
    // QKV GEMM
    gemm_tc<false><<<dim3(D3/128, MROWS/128), 256, GEMM_SMEM>>>(
        h, Wqkv_h, Wqkv_l, nullptr, nullptr, qkv, MROWS, D3, DD);
    // attention
    attn_kernel<<<dim3(TT/64, BB*HH), 64, attn_smem>>>(qkv, o);
    // proj + bias + residual(h)
    gemm_tc<false><<<dim3(DD/128, MROWS/128), 256, GEMM_SMEM>>>(
        o, Wp_h, Wp_l, bp, h, x2, MROWS, DD, DD);
    // LN2
    ln_kernel<<<MROWS, 256>>>(x2, g2, be2, h2);
    // FFN1 + bias + relu
    gemm_tc<true><<<dim3(D4/128, MROWS/128), 256, GEMM_SMEM>>>(
        h2, W1_h, W1_l, b1, nullptr, mid, MROWS, D4, DD);
    // FFN2 + bias + residual(h2)
    gemm_tc<false><<<dim3(DD/128, MROWS/128), 256, GEMM_SMEM>>>(
        mid, W2_h, W2_l, b2, h2, out, MROWS, DD, D4);
}

// round 4
// speedup vs baseline: 2.6018x; 1.5664x over previous
#include <cuda_runtime.h>
#include <cuda_bf16.h>
#include <cstdint>
#include <math.h>

// Problem constants
#define BB 4
#define TT 2048
#define DD 1024
#define HH 16
#define HS 64
#define MROWS (BB*TT)          // 8192
#define D3 (3*DD)              // 3072
#define D4 (4*DD)              // 4096

// ---------------- scratch (device globals; no allocs allowed) ----------------
__device__ float g_h  [MROWS*DD];     // LN1 output
__device__ float g_o  [MROWS*DD];     // attention output
__device__ float g_x2 [MROWS*DD];     // h + proj
__device__ float g_h2 [MROWS*DD];     // LN2 output
__device__ float g_mid[MROWS*D4];     // FFN hidden
__device__ __nv_bfloat16 g_qkv_h[MROWS*D3], g_qkv_l[MROWS*D3];   // qkv split-bf16
// bf16 hi/lo weights, [N][K] layout
__device__ __nv_bfloat16 g_Wqkv_h[D3*DD], g_Wqkv_l[D3*DD];
__device__ __nv_bfloat16 g_Wp_h [DD*DD], g_Wp_l [DD*DD];
__device__ __nv_bfloat16 g_W1_h [D4*DD], g_W1_l [D4*DD];
__device__ __nv_bfloat16 g_W2_h [DD*D4], g_W2_l [DD*D4];

// ======================= small PTX helpers ===================================
__device__ __forceinline__ uint32_t smem_u32(const void* p) {
    uint32_t a;
    asm("{ .reg .u64 t; cvta.to.shared.u64 t, %1; cvt.u32.u64 %0, t; }" : "=r"(a) : "l"(p));
    return a;
}
__device__ __forceinline__ void ldm4(uint32_t* r, uint32_t addr) {
    asm volatile("ldmatrix.sync.aligned.m8n8.x4.shared.b16 {%0,%1,%2,%3}, [%4];"
        : "=r"(r[0]), "=r"(r[1]), "=r"(r[2]), "=r"(r[3]) : "r"(addr));
}
__device__ __forceinline__ void ldm4t(uint32_t* r, uint32_t addr) {
    asm volatile("ldmatrix.sync.aligned.m8n8.x4.trans.shared.b16 {%0,%1,%2,%3}, [%4];"
        : "=r"(r[0]), "=r"(r[1]), "=r"(r[2]), "=r"(r[3]) : "r"(addr));
}
__device__ __forceinline__ void mma16816(float* d, const uint32_t* a, const uint32_t* b) {
    asm volatile("mma.sync.aligned.m16n8k16.row.col.f32.bf16.bf16.f32 "
        "{%0,%1,%2,%3}, {%4,%5,%6,%7}, {%8,%9}, {%0,%1,%2,%3};"
        : "+f"(d[0]), "+f"(d[1]), "+f"(d[2]), "+f"(d[3])
        : "r"(a[0]), "r"(a[1]), "r"(a[2]), "r"(a[3]), "r"(b[0]), "r"(b[1]));
}
__device__ __forceinline__ uint32_t pack_bf16(float a, float b) {
    __nv_bfloat16 x = __float2bfloat16(a), y = __float2bfloat16(b);
    return ((uint32_t)__bfloat16_as_ushort(y) << 16) | __bfloat16_as_ushort(x);
}

// ======== weight prep: transpose W[K][N] -> out[N][K] bf16 hi/lo =============
__global__ void prep_tr(const float* __restrict__ W,
                        __nv_bfloat16* __restrict__ oh,
                        __nv_bfloat16* __restrict__ ol, int K, int N) {
    __shared__ float ts[32][33];
    int n0 = blockIdx.x * 32, k0 = blockIdx.y * 32;
    int tx = threadIdx.x, ty = threadIdx.y;     // (32,8)
    #pragma unroll
    for (int i = 0; i < 4; i++)
        ts[ty + 8*i][tx] = W[(size_t)(k0 + ty + 8*i) * N + n0 + tx];
    __syncthreads();
    #pragma unroll
    for (int i = 0; i < 4; i++) {
        float v = ts[tx][ty + 8*i];
        size_t o = (size_t)(n0 + ty + 8*i) * K + k0 + tx;
        __nv_bfloat16 h = __float2bfloat16(v);
        oh[o] = h;
        ol[o] = __float2bfloat16(v - __bfloat162float(h));
    }
}

// QKV weights: Wq/Wk/Wv [H][D][HS] -> out[n=(sec,h,hs)][k=d] bf16 hi/lo
__global__ void prep_qkv(const float* __restrict__ Wq, const float* __restrict__ Wk,
                         const float* __restrict__ Wv,
                         __nv_bfloat16* __restrict__ oh, __nv_bfloat16* __restrict__ ol) {
    __shared__ float ts[32][33];
    int hs0 = blockIdx.x * 32;
    int d0  = blockIdx.y * 32;
    int z   = blockIdx.z;
    int sec = z >> 4, hh = z & 15;
    const float* W = (sec == 0) ? Wq : (sec == 1) ? Wk : Wv;
    int tx = threadIdx.x, ty = threadIdx.y;
    #pragma unroll
    for (int i = 0; i < 4; i++)
        ts[ty + 8*i][tx] = W[(size_t)hh * (DD*HS) + (size_t)(d0 + ty + 8*i) * HS + hs0 + tx];
    __syncthreads();
    #pragma unroll
    for (int i = 0; i < 4; i++) {
        float v = ts[tx][ty + 8*i];
        int n = sec * 1024 + hh * 64 + hs0 + ty + 8*i;
        size_t o = (size_t)n * DD + d0 + tx;
        __nv_bfloat16 h = __float2bfloat16(v);
        oh[o] = h;
        ol[o] = __float2bfloat16(v - __bfloat162float(h));
    }
}

// ---------------- LayerNorm -------------------------------------------------
__global__ void ln_kernel(const float* __restrict__ x,
                          const float* __restrict__ g,
                          const float* __restrict__ b,
                          float* __restrict__ y) {
    int row = blockIdx.x;
    int tid = threadIdx.x;
    const float4 v = *(const float4*)(x + (size_t)row * DD + tid * 4);
    float s  = v.x + v.y + v.z + v.w;
    float sq = v.x*v.x + v.y*v.y + v.z*v.z + v.w*v.w;
    #pragma unroll
    for (int o = 16; o > 0; o >>= 1) {
        s  += __shfl_xor_sync(0xffffffffu, s,  o);
        sq += __shfl_xor_sync(0xffffffffu, sq, o);
    }
    __shared__ float ws[8], wq[8];
    int wid = tid >> 5, lid = tid & 31;
    if (lid == 0) { ws[wid] = s; wq[wid] = sq; }
    __syncthreads();
    if (wid == 0) {
        float a = (lid < 8) ? ws[lid] : 0.f;
        float c = (lid < 8) ? wq[lid] : 0.f;
        #pragma unroll
        for (int o = 4; o > 0; o >>= 1) {
            a += __shfl_xor_sync(0xffffffffu, a, o);
            c += __shfl_xor_sync(0xffffffffu, c, o);
        }
        if (lid == 0) { ws[0] = a; wq[0] = c; }
    }
    __syncthreads();
    float mu  = ws[0] * (1.0f / DD);
    float var = wq[0] * (1.0f / DD) - mu * mu;
    float inv = rsqrtf(var + 1e-5f);
    const float4 gg = *(const float4*)(g + tid * 4);
    const float4 bb = *(const float4*)(b + tid * 4);
    float4 o4;
    o4.x = (v.x - mu) * inv * gg.x + bb.x;
    o4.y = (v.y - mu) * inv * gg.y + bb.y;
    o4.z = (v.z - mu) * inv * gg.z + bb.z;
    o4.w = (v.w - mu) * inv * gg.w + bb.w;
    *(float4*)(y + (size_t)row * DD + tid * 4) = o4;
}

// ============ mma.sync GEMM: C[M,N] = A[M,K] @ Wt[N,K]^T =====================
// split-bf16, fp32 accum: D += Ah*Bh + Al*Bh + Ah*Bl
// CTA 128x128, 8 warps (4Mx2N), warp tile 32x64, K-chunk 32, double-buffered.
// If EMITBF: write bf16 hi/lo split instead of fp32 C.
#define LDT 40                         // smem row stride in bf16 elements (80B)
#define TILE_BYTES (128*LDT*2)         // 10240
#define STAGE_BYTES (4*TILE_BYTES)     // Ah, Al, Bh, Bl = 40960
#define GEMM_SMEM (2*STAGE_BYTES)      // 81920

template <bool RELU, bool EMITBF>
__global__ __launch_bounds__(256)
void gemm_tc(const float* __restrict__ A,
             const __nv_bfloat16* __restrict__ Bh, const __nv_bfloat16* __restrict__ Bl,
             const float* __restrict__ bias, const float* __restrict__ res,
             float* __restrict__ C,
             __nv_bfloat16* __restrict__ Oh, __nv_bfloat16* __restrict__ Ol,
             int M, int N, int K) {
    extern __shared__ char smem[];
    uint32_t sb = smem_u32(smem);
    int tid = threadIdx.x, wid = tid >> 5, lane = tid & 31;
    int wm = wid >> 1, wn = wid & 1;
    int m0 = blockIdx.y * 128, n0 = blockIdx.x * 128;

    int lr   = tid >> 1;
    int lseg = (tid & 1) * 16;

    const float* Ap0 = A + (size_t)(m0 + lr) * K + lseg;
    const __nv_bfloat16* Bhp0 = Bh + (size_t)(n0 + lr) * K + lseg;
    const __nv_bfloat16* Blp0 = Bl + (size_t)(n0 + lr) * K + lseg;

    float acc[2][8][4];
    #pragma unroll
    for (int i = 0; i < 2; i++)
        #pragma unroll
        for (int j = 0; j < 8; j++)
            #pragma unroll
            for (int q = 0; q < 4; q++) acc[i][j][q] = 0.f;

    const int nch = K >> 5;
    float4 pa[4];
    uint4  pbh[2], pbl[2];

    #pragma unroll
    for (int i = 0; i < 4; i++) pa[i] = *(const float4*)(Ap0 + i * 4);
    #pragma unroll
    for (int i = 0; i < 2; i++) {
        pbh[i] = *(const uint4*)(Bhp0 + i * 8);
        pbl[i] = *(const uint4*)(Blp0 + i * 8);
    }
    {
        char* st = smem;
        uint32_t ro = (uint32_t)(lr * LDT + lseg) * 2;
        #pragma unroll
        for (int i = 0; i < 4; i++) {
            float4 v = pa[i];
            __nv_bfloat16 h0 = __float2bfloat16(v.x), h1 = __float2bfloat16(v.y);
            __nv_bfloat16 h2 = __float2bfloat16(v.z), h3 = __float2bfloat16(v.w);
            uint2 hp, lp;
            hp.x = ((uint32_t)__bfloat16_as_ushort(h1) << 16) | __bfloat16_as_ushort(h0);
            hp.y = ((uint32_t)__bfloat16_as_ushort(h3) << 16) | __bfloat16_as_ushort(h2);
            lp.x = pack_bf16(v.x - __bfloat162float(h0), v.y - __bfloat162float(h1));
            lp.y = pack_bf16(v.z - __bfloat162float(h2), v.w - __bfloat162float(h3));
            *(uint2*)(st + 0*TILE_BYTES + ro + i * 8) = hp;
            *(uint2*)(st + 1*TILE_BYTES + ro + i * 8) = lp;
        }
        #pragma unroll
        for (int i = 0; i < 2; i++) {
            *(uint4*)(st + 2*TILE_BYTES + ro + i * 16) = pbh[i];
            *(uint4*)(st + 3*TILE_BYTES + ro + i * 16) = pbl[i];
        }
    }
    __syncthreads();

    int a_r = ((lane >> 3) & 1) * 8 + (lane & 7);
    int a_c = (lane >> 4) * 8;
    int b_r = (lane >> 4) * 8 + (lane & 7);
    int b_c = ((lane >> 3) & 1) * 8;

    for (int c = 0; c < nch; c++) {
        if (c + 1 < nch) {
            int off = (c + 1) * 32;
            #pragma unroll
            for (int i = 0; i < 4; i++) pa[i] = *(const float4*)(Ap0 + off + i * 4);
            #pragma unroll
            for (int i = 0; i < 2; i++) {
                pbh[i] = *(const uint4*)(Bhp0 + off + i * 8);
                pbl[i] = *(const uint4*)(Blp0 + off + i * 8);
            }
        }
        uint32_t stage = sb + (uint32_t)(c & 1) * STAGE_BYTES;
        #pragma unroll
        for (int k16 = 0; k16 < 32; k16 += 16) {
            uint32_t ah[2][4], al[2][4];
            #pragma unroll
            for (int mt = 0; mt < 2; mt++) {
                uint32_t ao = (uint32_t)((wm*32 + mt*16 + a_r) * LDT + k16 + a_c) * 2;
                ldm4(ah[mt], stage + 0*TILE_BYTES + ao);
                ldm4(al[mt], stage + 1*TILE_BYTES + ao);
            }
            #pragma unroll
            for (int nt = 0; nt < 4; nt++) {
                uint32_t bh[4], bl[4];
                uint32_t bo = (uint32_t)((wn*64 + nt*16 + b_r) * LDT + k16 + b_c) * 2;
                ldm4(bh, stage + 2*TILE_BYTES + bo);
                ldm4(bl, stage + 3*TILE_BYTES + bo);
                #pragma unroll
                for (int mt = 0; mt < 2; mt++) {
                    mma16816(acc[mt][2*nt+0], ah[mt], bh + 0);
                    mma16816(acc[mt][2*nt+0], al[mt], bh + 0);
                    mma16816(acc[mt][2*nt+0], ah[mt], bl + 0);
                    mma16816(acc[mt][2*nt+1], ah[mt], bh + 2);
                    mma16816(acc[mt][2*nt+1], al[mt], bh + 2);
                    mma16816(acc[mt][2*nt+1], ah[mt], bl + 2);
                }
            }
        }
        if (c + 1 < nch) {
            char* st = smem + ((c + 1) & 1) * STAGE_BYTES;
            uint32_t ro = (uint32_t)(lr * LDT + lseg) * 2;
            #pragma unroll
            for (int i = 0; i < 4; i++) {
                float4 v = pa[i];
                __nv_bfloat16 h0 = __float2bfloat16(v.x), h1 = __float2bfloat16(v.y);
                __nv_bfloat16 h2 = __float2bfloat16(v.z), h3 = __float2bfloat16(v.w);
                uint2 hp, lp;
                hp.x = ((uint32_t)__bfloat16_as_ushort(h1) << 16) | __bfloat16_as_ushort(h0);
                hp.y = ((uint32_t)__bfloat16_as_ushort(h3) << 16) | __bfloat16_as_ushort(h2);
                lp.x = pack_bf16(v.x - __bfloat162float(h0), v.y - __bfloat162float(h1));
                lp.y = pack_bf16(v.z - __bfloat162float(h2), v.w - __bfloat162float(h3));
                *(uint2*)(st + 0*TILE_BYTES + ro + i * 8) = hp;
                *(uint2*)(st + 1*TILE_BYTES + ro + i * 8) = lp;
            }
            #pragma unroll
            for (int i = 0; i < 2; i++) {
                *(uint4*)(st + 2*TILE_BYTES + ro + i * 16) = pbh[i];
                *(uint4*)(st + 3*TILE_BYTES + ro + i * 16) = pbl[i];
            }
        }
        __syncthreads();
    }

    // ---- epilogue ----
    int trow = lane >> 2, tcol = (lane & 3) * 2;
    #pragma unroll
    for (int mt = 0; mt < 2; mt++) {
        #pragma unroll
        for (int rr = 0; rr < 2; rr++) {
            int row = m0 + wm*32 + mt*16 + rr*8 + trow;
            #pragma unroll
            for (int j = 0; j < 8; j++) {
                int col = n0 + wn*64 + j*8 + tcol;
                float v0 = acc[mt][j][rr*2+0];
                float v1 = acc[mt][j][rr*2+1];
                if (bias) { v0 += bias[col]; v1 += bias[col+1]; }
                if (RELU) { v0 = fmaxf(v0, 0.f); v1 = fmaxf(v1, 0.f); }
                if (res) {
                    const float2 r2 = *(const float2*)(res + (size_t)row * N + col);
                    v0 += r2.x; v1 += r2.y;
                }
                if (EMITBF) {
                    __nv_bfloat16 h0 = __float2bfloat16(v0), h1 = __float2bfloat16(v1);
                    uint32_t hp = ((uint32_t)__bfloat16_as_ushort(h1) << 16) | __bfloat16_as_ushort(h0);
                    uint32_t lp = pack_bf16(v0 - __bfloat162float(h0), v1 - __bfloat162float(h1));
                    *(uint32_t*)(Oh + (size_t)row * N + col) = hp;
                    *(uint32_t*)(Ol + (size_t)row * N + col) = lp;
                } else {
                    float2 o2; o2.x = v0; o2.y = v1;
                    *(float2*)(C + (size_t)row * N + col) = o2;
                }
            }
        }
    }
}

// ============ Tensor-core causal flash attention ============================
// CTA: 128 query rows of one (b,h); 8 warps x 16 rows. K-tile = 64 keys.
// S = (Qh+Ql)(Kh+Kl)^T (3-term), softmax online, O += P(bf16) x (Vh+Vl) (2-term)
#define VST 72                               // smem row stride (elements)
#define ATILE_B (64*VST*2)                   // 9216 B per matrix tile
#define ASTAGE_B (4*ATILE_B)                 // Kh,Kl,Vh,Vl = 36864
#define ATTN_SMEM2 (2*ASTAGE_B)              // 73728

__global__ __launch_bounds__(256)
void attn_tc(const __nv_bfloat16* __restrict__ qh,
             const __nv_bfloat16* __restrict__ ql,
             float* __restrict__ o) {
    extern __shared__ char smem[];
    uint32_t sb = smem_u32(smem);
    int tid = threadIdx.x, w = tid >> 5, lane = tid & 31;
    int qb = (int)(gridDim.x - 1 - blockIdx.x);      // big tiles first
    int b  = blockIdx.y >> 4, h = blockIdx.y & 15;
    int qbase = qb * 128;
    int wrow  = qbase + w * 16;                      // warp's first q row
    int trow = lane >> 2, tc2 = (lane & 3) * 2;
    int gr0 = wrow + trow, gr1 = gr0 + 8;            // the two rows this thread owns

    // ---- load Q fragments (A-layout) straight from gmem ----
    uint32_t Qh[4][4], Ql[4][4];
    {
        size_t r0 = ((size_t)b * TT + gr0) * D3 + h * 64;
        size_t r1 = ((size_t)b * TT + gr1) * D3 + h * 64;
        #pragma unroll
        for (int ks = 0; ks < 4; ks++) {
            int c0 = ks * 16 + tc2;
            Qh[ks][0] = *(const uint32_t*)(qh + r0 + c0);
            Qh[ks][1] = *(const uint32_t*)(qh + r1 + c0);
            Qh[ks][2] = *(const uint32_t*)(qh + r0 + c0 + 8);
            Qh[ks][3] = *(const uint32_t*)(qh + r1 + c0 + 8);
            Ql[ks][0] = *(const uint32_t*)(ql + r0 + c0);
            Ql[ks][1] = *(const uint32_t*)(ql + r1 + c0);
            Ql[ks][2] = *(const uint32_t*)(ql + r0 + c0 + 8);
            Ql[ks][3] = *(const uint32_t*)(ql + r1 + c0 + 8);
        }
    }

    float oacc[8][4];
    #pragma unroll
    for (int j = 0; j < 8; j++)
        #pragma unroll
        for (int q = 0; q < 4; q++) oacc[j][q] = 0.f;
    float m0 = -1e30f, m1 = -1e30f, l0 = 0.f, l1 = 0.f;

    const int nkt = 2 * qb + 2;

    // gmem tile-load coords: 4 threads per key row, 16 elements each
    int lrow = tid >> 2, lseg = (tid & 3) * 16;
    size_t kcol = 1024 + h * 64 + lseg;
    size_t vcol = 2048 + h * 64 + lseg;
    uint32_t ro = (uint32_t)(lrow * VST + lseg) * 2;

    uint4 pkh[2], pkl[2], pvh[2], pvl[2];

    // prologue: load tile 0
    {
        size_t base = ((size_t)b * TT + lrow) * D3;
        #pragma unroll
        for (int i = 0; i < 2; i++) {
            pkh[i] = *(const uint4*)(qh + base + kcol + i * 8);
            pkl[i] = *(const uint4*)(ql + base + kcol + i * 8);
            pvh[i] = *(const uint4*)(qh + base + vcol + i * 8);
            pvl[i] = *(const uint4*)(ql + base + vcol + i * 8);
        }
        char* st = smem;
        #pragma unroll
        for (int i = 0; i < 2; i++) {
            *(uint4*)(st + 0*ATILE_B + ro + i * 16) = pkh[i];
            *(uint4*)(st + 1*ATILE_B + ro + i * 16) = pkl[i];
            *(uint4*)(st + 2*ATILE_B + ro + i * 16) = pvh[i];
            *(uint4*)(st + 3*ATILE_B + ro + i * 16) = pvl[i];
        }
    }
    __syncthreads();

    // ldmatrix lane coords
    int kb_r = (lane >> 4) * 8 + (lane & 7);     // K frag: row(key), + ng*16
    int kb_c = ((lane >> 3) & 1) * 8;            //        col(dim), + ks*16
    int vb_r = ((lane >> 3) & 1) * 8 + (lane & 7); // V frag (trans): row(key), + ks*16
    int vb_c = (lane >> 4) * 8;                    //                col(dim), + nd*16

    for (int kt = 0; kt < nkt; kt++) {
        int kbkey = kt * 64;
        // prefetch next tile
        if (kt + 1 < nkt) {
            size_t base = ((size_t)b * TT + (kt + 1) * 64 + lrow) * D3;
            #pragma unroll
            for (int i = 0; i < 2; i++) {
                pkh[i] = *(const uint4*)(qh + base + kcol + i * 8);
                pkl[i] = *(const uint4*)(ql + base + kcol + i * 8);
                pvh[i] = *(const uint4*)(qh + base + vcol + i * 8);
                pvl[i] = *(const uint4*)(ql + base + vcol + i * 8);
            }
        }
        uint32_t stage = sb + (uint32_t)(kt & 1) * ASTAGE_B;

        // ---- S = Q K^T (3-term split) ----
        float sacc[8][4];
        #pragma unroll
        for (int j = 0; j < 8; j++)
            #pragma unroll
            for (int q = 0; q < 4; q++) sacc[j][q] = 0.f;
        #pragma unroll
        for (int ks = 0; ks < 4; ks++) {
            #pragma unroll
            for (int ng = 0; ng < 4; ng++) {
                uint32_t kh[4], kl[4];
                uint32_t ko = (uint32_t)((ng*16 + kb_r) * VST + ks*16 + kb_c) * 2;
                ldm4(kh, stage + 0*ATILE_B + ko);
                ldm4(kl, stage + 1*ATILE_B + ko);
                mma16816(sacc[2*ng+0], Qh[ks], kh + 0);
                mma16816(sacc[2*ng+0], Ql[ks], kh + 0);
                mma16816(sacc[2*ng+0], Qh[ks], kl + 0);
                mma16816(sacc[2*ng+1], Qh[ks], kh + 2);
                mma16816(sacc[2*ng+1], Ql[ks], kh + 2);
                mma16816(sacc[2*ng+1], Qh[ks], kl + 2);
            }
        }
        // ---- scale + causal mask ----
        const float scale = 0.03125f;    // D^-0.5
        #pragma unroll
        for (int j = 0; j < 8; j++)
            #pragma unroll
            for (int q = 0; q < 4; q++) sacc[j][q] *= scale;
        if (kbkey + 63 > wrow) {
            #pragma unroll
            for (int j = 0; j < 8; j++) {
                int c0 = kbkey + j*8 + tc2;
                if (c0     > gr0) sacc[j][0] = -1e30f;
                if (c0 + 1 > gr0) sacc[j][1] = -1e30f;
                if (c0     > gr1) sacc[j][2] = -1e30f;
                if (c0 + 1 > gr1) sacc[j][3] = -1e30f;
            }
        }
        // ---- online softmax ----
        float mt0 = -1e30f, mt1 = -1e30f;
        #pragma unroll
        for (int j = 0; j < 8; j++) {
            mt0 = fmaxf(mt0, fmaxf(sacc[j][0], sacc[j][1]));
            mt1 = fmaxf(mt1, fmaxf(sacc[j][2], sacc[j][3]));
        }
        mt0 = fmaxf(mt0, __shfl_xor_sync(0xffffffffu, mt0, 1));
        mt0 = fmaxf(mt0, __shfl_xor_sync(0xffffffffu, mt0, 2));
        mt1 = fmaxf(mt1, __shfl_xor_sync(0xffffffffu, mt1, 1));
        mt1 = fmaxf(mt1, __shfl_xor_sync(0xffffffffu, mt1, 2));
        float mn0 = fmaxf(m0, mt0), mn1 = fmaxf(m1, mt1);
        float f0 = __expf(m0 - mn0), f1 = __expf(m1 - mn1);
        float rs0 = 0.f, rs1 = 0.f;
        #pragma unroll
        for (int j = 0; j < 8; j++) {
            sacc[j][0] = __expf(sacc[j][0] - mn0);
            sacc[j][1] = __expf(sacc[j][1] - mn0);
            sacc[j][2] = __expf(sacc[j][2] - mn1);
            sacc[j][3] = __expf(sacc[j][3] - mn1);
            rs0 += sacc[j][0] + sacc[j][1];
            rs1 += sacc[j][2] + sacc[j][3];
        }
        rs0 += __shfl_xor_sync(0xffffffffu, rs0, 1);
        rs0 += __shfl_xor_sync(0xffffffffu, rs0, 2);
        rs1 += __shfl_xor_sync(0xffffffffu, rs1, 1);
        rs1 += __shfl_xor_sync(0xffffffffu, rs1, 2);
        l0 = l0 * f0 + rs0;  l1 = l1 * f1 + rs1;
        m0 = mn0;  m1 = mn1;
        #pragma unroll
        for (int j = 0; j < 8; j++) {
            oacc[j][0] *= f0; oacc[j][1] *= f0;
            oacc[j][2] *= f1; oacc[j][3] *= f1;
        }
        // ---- O += P * V (P from sacc regs; V split 2-term) ----
        #pragma unroll
        for (int ks = 0; ks < 4; ks++) {
            uint32_t pfr[4];
            pfr[0] = pack_bf16(sacc[2*ks  ][0], sacc[2*ks  ][1]);
            pfr[1] = pack_bf16(sacc[2*ks  ][2], sacc[2*ks  ][3]);
            pfr[2] = pack_bf16(sacc[2*ks+1][0], sacc[2*ks+1][1]);
            pfr[3] = pack_bf16(sacc[2*ks+1][2], sacc[2*ks+1][3]);
            #pragma unroll
            for (int nd = 0; nd < 4; nd++) {
                uint32_t vh[4], vl[4];
                uint32_t vo = (uint32_t)((ks*16 + vb_r) * VST + nd*16 + vb_c) * 2;
                ldm4t(vh, stage + 2*ATILE_B + vo);
                ldm4t(vl, stage + 3*ATILE_B + vo);
                mma16816(oacc[2*nd+0], pfr, vh + 0);
                mma16816(oacc[2*nd+0], pfr, vl + 0);
                mma16816(oacc[2*nd+1], pfr, vh + 2);
                mma16816(oacc[2*nd+1], pfr, vl + 2);
            }
        }
        // store next tile
        if (kt + 1 < nkt) {
            char* st = smem + ((kt + 1) & 1) * ASTAGE_B;
            #pragma unroll
            for (int i = 0; i < 2; i++) {
                *(uint4*)(st + 0*ATILE_B + ro + i * 16) = pkh[i];
                *(uint4*)(st + 1*ATILE_B + ro + i * 16) = pkl[i];
                *(uint4*)(st + 2*ATILE_B + ro + i * 16) = pvh[i];
                *(uint4*)(st + 3*ATILE_B + ro + i * 16) = pvl[i];
            }
        }
        __syncthreads();
    }

    // ---- write O ----
    float rl0 = 1.0f / l0, rl1 = 1.0f / l1;
    size_t ob0 = ((size_t)b * TT + gr0) * DD + h * 64;
    size_t ob1 = ((size_t)b * TT + gr1) * DD + h * 64;
    #pragma unroll
    for (int jd = 0; jd < 8; jd++) {
        float2 v0; v0.x = oacc[jd][0] * rl0; v0.y = oacc[jd][1] * rl0;
        float2 v1; v1.x = oacc[jd][2] * rl1; v1.y = oacc[jd][3] * rl1;
        *(float2*)(o + ob0 + jd*8 + tc2) = v0;
        *(float2*)(o + ob1 + jd*8 + tc2) = v1;
    }
}

// ---------------- launch ------------------------------------------------------
extern "C" void kernel_launch(void* const* d_in, const int* in_sizes, int n_in,
                              void* d_out, int out_size) {
    const float* x   = (const float*)d_in[0];
    const float* Wq  = (const float*)d_in[1];
    const float* Wk  = (const float*)d_in[2];
    const float* Wv  = (const float*)d_in[3];
    const float* Wp  = (const float*)d_in[4];
    const float* bp  = (const float*)d_in[5];
    const float* W1  = (const float*)d_in[6];
    const float* b1  = (const float*)d_in[7];
    const float* W2  = (const float*)d_in[8];
    const float* b2  = (const float*)d_in[9];
    const float* g1  = (const float*)d_in[10];
    const float* be1 = (const float*)d_in[11];
    const float* g2  = (const float*)d_in[12];
    const float* be2 = (const float*)d_in[13];
    float* out = (float*)d_out;

    float *h, *o, *x2, *h2, *mid;
    cudaGetSymbolAddress((void**)&h,   g_h);
    cudaGetSymbolAddress((void**)&o,   g_o);
    cudaGetSymbolAddress((void**)&x2,  g_x2);
    cudaGetSymbolAddress((void**)&h2,  g_h2);
    cudaGetSymbolAddress((void**)&mid, g_mid);
    __nv_bfloat16 *qkvh, *qkvl;
    cudaGetSymbolAddress((void**)&qkvh, g_qkv_h);
    cudaGetSymbolAddress((void**)&qkvl, g_qkv_l);
    __nv_bfloat16 *Wqkv_h, *Wqkv_l, *Wp_h, *Wp_l, *W1_h, *W1_l, *W2_h, *W2_l;
    cudaGetSymbolAddress((void**)&Wqkv_h, g_Wqkv_h);
    cudaGetSymbolAddress((void**)&Wqkv_l, g_Wqkv_l);
    cudaGetSymbolAddress((void**)&Wp_h, g_Wp_h);
    cudaGetSymbolAddress((void**)&Wp_l, g_Wp_l);
    cudaGetSymbolAddress((void**)&W1_h, g_W1_h);
    cudaGetSymbolAddress((void**)&W1_l, g_W1_l);
    cudaGetSymbolAddress((void**)&W2_h, g_W2_h);
    cudaGetSymbolAddress((void**)&W2_l, g_W2_l);

    cudaFuncSetAttribute(attn_tc,
                         cudaFuncAttributeMaxDynamicSharedMemorySize, ATTN_SMEM2);
    cudaFuncSetAttribute(gemm_tc<false,false>,
                         cudaFuncAttributeMaxDynamicSharedMemorySize, GEMM_SMEM);
    cudaFuncSetAttribute(gemm_tc<true,false>,
                         cudaFuncAttributeMaxDynamicSharedMemorySize, GEMM_SMEM);
    cudaFuncSetAttribute(gemm_tc<false,true>,
                         cudaFuncAttributeMaxDynamicSharedMemorySize, GEMM_SMEM);

    dim3 tb(32, 8);
    prep_qkv<<<dim3(2, 32, 48), tb>>>(Wq, Wk, Wv, Wqkv_h, Wqkv_l);
    prep_tr<<<dim3(DD/32, DD/32), tb>>>(Wp, Wp_h, Wp_l, DD, DD);
    prep_tr<<<dim3(D4/32, DD/32), tb>>>(W1, W1_h, W1_l, DD, D4);
    prep_tr<<<dim3(DD/32, D4/32), tb>>>(W2, W2_h, W2_l, D4, DD);

    // LN1
    ln_kernel<<<MROWS, 256>>>(x, g1, be1, h);
    // QKV GEMM -> split-bf16 qkv
    gemm_tc<false,true><<<dim3(D3/128, MROWS/128), 256, GEMM_SMEM>>>(
        h, Wqkv_h, Wqkv_l, nullptr, nullptr, nullptr, qkvh, qkvl, MROWS, D3, DD);
    // tensor-core attention
    attn_tc<<<dim3(TT/128, BB*HH), 256, ATTN_SMEM2>>>(qkvh, qkvl, o);
    // proj + bias + residual(h)
    gemm_tc<false,false><<<dim3(DD/128, MROWS/128), 256, GEMM_SMEM>>>(
        o, Wp_h, Wp_l, bp, h, x2, nullptr, nullptr, MROWS, DD, DD);
    // LN2
    ln_kernel<<<MROWS, 256>>>(x2, g2, be2, h2);
    // FFN1 + bias + relu
    gemm_tc<true,false><<<dim3(D4/128, MROWS/128), 256, GEMM_SMEM>>>(
        h2, W1_h, W1_l, b1, nullptr, mid, nullptr, nullptr, MROWS, D4, DD);
    // FFN2 + bias + residual(h2)
    gemm_tc<false,false><<<dim3(DD/128, MROWS/128), 256, GEMM_SMEM>>>(
        mid, W2_h, W2_l, b2, h2, out, nullptr, nullptr, MROWS, DD, D4);
}

// round 5
// speedup vs baseline: 2.8159x; 1.0823x over previous
#include <cuda_runtime.h>
#include <cuda_bf16.h>
#include <cstdint>
#include <math.h>

// Problem constants
#define BB 4
#define TT 2048
#define DD 1024
#define HH 16
#define HS 64
#define MROWS (BB*TT)          // 8192
#define D3 (3*DD)              // 3072
#define D4 (4*DD)              // 4096

typedef __nv_bfloat16 bf16;

// ---------------- scratch (device globals; no allocs allowed) ----------------
__device__ bf16 g_hh [MROWS*DD], g_hl [MROWS*DD];     // LN1 out pair
__device__ bf16 g_oh [MROWS*DD], g_ol [MROWS*DD];     // attention out pair
__device__ bf16 g_x2h[MROWS*DD], g_x2l[MROWS*DD];     // h + proj pair
__device__ bf16 g_h2h[MROWS*DD], g_h2l[MROWS*DD];     // LN2 out pair
__device__ bf16 g_mdh[MROWS*D4], g_mdl[MROWS*D4];     // FFN hidden pair
__device__ bf16 g_qkv_h[MROWS*D3], g_qkv_l[MROWS*D3]; // qkv pair
// bf16 hi/lo weights, [N][K] layout
__device__ bf16 g_Wqkv_h[D3*DD], g_Wqkv_l[D3*DD];
__device__ bf16 g_Wp_h [DD*DD], g_Wp_l [DD*DD];
__device__ bf16 g_W1_h [D4*DD], g_W1_l [D4*DD];
__device__ bf16 g_W2_h [DD*D4], g_W2_l [DD*D4];

// ======================= small PTX helpers ===================================
__device__ __forceinline__ uint32_t smem_u32(const void* p) {
    uint32_t a;
    asm("{ .reg .u64 t; cvta.to.shared.u64 t, %1; cvt.u32.u64 %0, t; }" : "=r"(a) : "l"(p));
    return a;
}
__device__ __forceinline__ void ldm4(uint32_t* r, uint32_t addr) {
    asm volatile("ldmatrix.sync.aligned.m8n8.x4.shared.b16 {%0,%1,%2,%3}, [%4];"
        : "=r"(r[0]), "=r"(r[1]), "=r"(r[2]), "=r"(r[3]) : "r"(addr));
}
__device__ __forceinline__ void ldm4t(uint32_t* r, uint32_t addr) {
    asm volatile("ldmatrix.sync.aligned.m8n8.x4.trans.shared.b16 {%0,%1,%2,%3}, [%4];"
        : "=r"(r[0]), "=r"(r[1]), "=r"(r[2]), "=r"(r[3]) : "r"(addr));
}
__device__ __forceinline__ void mma16816(float* d, const uint32_t* a, const uint32_t* b) {
    asm volatile("mma.sync.aligned.m16n8k16.row.col.f32.bf16.bf16.f32 "
        "{%0,%1,%2,%3}, {%4,%5,%6,%7}, {%8,%9}, {%0,%1,%2,%3};"
        : "+f"(d[0]), "+f"(d[1]), "+f"(d[2]), "+f"(d[3])
        : "r"(a[0]), "r"(a[1]), "r"(a[2]), "r"(a[3]), "r"(b[0]), "r"(b[1]));
}
__device__ __forceinline__ uint32_t pack_bf16(float a, float b) {
    bf16 x = __float2bfloat16(a), y = __float2bfloat16(b);
    return ((uint32_t)__bfloat16_as_ushort(y) << 16) | __bfloat16_as_ushort(x);
}
__device__ __forceinline__ void split2(float a, float b, uint32_t& hp, uint32_t& lp) {
    bf16 h0 = __float2bfloat16(a), h1 = __float2bfloat16(b);
    hp = ((uint32_t)__bfloat16_as_ushort(h1) << 16) | __bfloat16_as_ushort(h0);
    lp = pack_bf16(a - __bfloat162float(h0), b - __bfloat162float(h1));
}
__device__ __forceinline__ void cpa16(uint32_t dst, const void* src) {
    asm volatile("cp.async.cg.shared.global [%0], [%1], 16;" :: "r"(dst), "l"(src));
}
#define CP_COMMIT() asm volatile("cp.async.commit_group;" ::: "memory")
#define CP_WAIT1()  asm volatile("cp.async.wait_group 1;" ::: "memory")
#define CP_WAIT0()  asm volatile("cp.async.wait_group 0;" ::: "memory")

// ======== weight prep: transpose W[K][N] -> out[N][K] bf16 hi/lo =============
__global__ void prep_tr(const float* __restrict__ W,
                        bf16* __restrict__ oh, bf16* __restrict__ ol, int K, int N) {
    __shared__ float ts[32][33];
    int n0 = blockIdx.x * 32, k0 = blockIdx.y * 32;
    int tx = threadIdx.x, ty = threadIdx.y;     // (32,8)
    #pragma unroll
    for (int i = 0; i < 4; i++)
        ts[ty + 8*i][tx] = W[(size_t)(k0 + ty + 8*i) * N + n0 + tx];
    __syncthreads();
    #pragma unroll
    for (int i = 0; i < 4; i++) {
        float v = ts[tx][ty + 8*i];
        size_t o = (size_t)(n0 + ty + 8*i) * K + k0 + tx;
        bf16 h = __float2bfloat16(v);
        oh[o] = h;
        ol[o] = __float2bfloat16(v - __bfloat162float(h));
    }
}

// QKV weights: Wq/Wk/Wv [H][D][HS] -> out[n=(sec,h,hs)][k=d] bf16 hi/lo
__global__ void prep_qkv(const float* __restrict__ Wq, const float* __restrict__ Wk,
                         const float* __restrict__ Wv,
                         bf16* __restrict__ oh, bf16* __restrict__ ol) {
    __shared__ float ts[32][33];
    int hs0 = blockIdx.x * 32;
    int d0  = blockIdx.y * 32;
    int z   = blockIdx.z;
    int sec = z >> 4, hh = z & 15;
    const float* W = (sec == 0) ? Wq : (sec == 1) ? Wk : Wv;
    int tx = threadIdx.x, ty = threadIdx.y;
    #pragma unroll
    for (int i = 0; i < 4; i++)
        ts[ty + 8*i][tx] = W[(size_t)hh * (DD*HS) + (size_t)(d0 + ty + 8*i) * HS + hs0 + tx];
    __syncthreads();
    #pragma unroll
    for (int i = 0; i < 4; i++) {
        float v = ts[tx][ty + 8*i];
        int n = sec * 1024 + hh * 64 + hs0 + ty + 8*i;
        size_t o = (size_t)n * DD + d0 + tx;
        bf16 h = __float2bfloat16(v);
        oh[o] = h;
        ol[o] = __float2bfloat16(v - __bfloat162float(h));
    }
}

// ---------------- LayerNorm: fp32 or pair input -> pair output ---------------
template <bool PAIRIN>
__global__ void ln_kernel(const float* __restrict__ x,
                          const bf16* __restrict__ xh, const bf16* __restrict__ xl,
                          const float* __restrict__ g, const float* __restrict__ b,
                          bf16* __restrict__ yh, bf16* __restrict__ yl) {
    int row = blockIdx.x;
    int tid = threadIdx.x;
    float4 v;
    if (PAIRIN) {
        const uint2 hv = *(const uint2*)(xh + (size_t)row * DD + tid * 4);
        const uint2 lv = *(const uint2*)(xl + (size_t)row * DD + tid * 4);
        __nv_bfloat162 h0 = *(const __nv_bfloat162*)&hv.x;
        __nv_bfloat162 h1 = *(const __nv_bfloat162*)&hv.y;
        __nv_bfloat162 l0 = *(const __nv_bfloat162*)&lv.x;
        __nv_bfloat162 l1 = *(const __nv_bfloat162*)&lv.y;
        v.x = __bfloat162float(h0.x) + __bfloat162float(l0.x);
        v.y = __bfloat162float(h0.y) + __bfloat162float(l0.y);
        v.z = __bfloat162float(h1.x) + __bfloat162float(l1.x);
        v.w = __bfloat162float(h1.y) + __bfloat162float(l1.y);
    } else {
        v = *(const float4*)(x + (size_t)row * DD + tid * 4);
    }
    float s  = v.x + v.y + v.z + v.w;
    float sq = v.x*v.x + v.y*v.y + v.z*v.z + v.w*v.w;
    #pragma unroll
    for (int o = 16; o > 0; o >>= 1) {
        s  += __shfl_xor_sync(0xffffffffu, s,  o);
        sq += __shfl_xor_sync(0xffffffffu, sq, o);
    }
    __shared__ float ws[8], wq[8];
    int wid = tid >> 5, lid = tid & 31;
    if (lid == 0) { ws[wid] = s; wq[wid] = sq; }
    __syncthreads();
    if (wid == 0) {
        float a = (lid < 8) ? ws[lid] : 0.f;
        float c = (lid < 8) ? wq[lid] : 0.f;
        #pragma unroll
        for (int o = 4; o > 0; o >>= 1) {
            a += __shfl_xor_sync(0xffffffffu, a, o);
            c += __shfl_xor_sync(0xffffffffu, c, o);
        }
        if (lid == 0) { ws[0] = a; wq[0] = c; }
    }
    __syncthreads();
    float mu  = ws[0] * (1.0f / DD);
    float var = wq[0] * (1.0f / DD) - mu * mu;
    float inv = rsqrtf(var + 1e-5f);
    const float4 gg = *(const float4*)(g + tid * 4);
    const float4 bb = *(const float4*)(b + tid * 4);
    float o0 = (v.x - mu) * inv * gg.x + bb.x;
    float o1 = (v.y - mu) * inv * gg.y + bb.y;
    float o2 = (v.z - mu) * inv * gg.z + bb.z;
    float o3 = (v.w - mu) * inv * gg.w + bb.w;
    uint2 hp, lp;
    split2(o0, o1, hp.x, lp.x);
    split2(o2, o3, hp.y, lp.y);
    *(uint2*)(yh + (size_t)row * DD + tid * 4) = hp;
    *(uint2*)(yl + (size_t)row * DD + tid * 4) = lp;
}

// ============ mma.sync GEMM: C[M,N] = (Ah+Al)[M,K] @ (Bh+Bl)[N,K]^T ==========
// 3-term split-bf16 fp32 accum. cp.async 2-stage pipeline.
#define LDT 40                         // smem row stride in bf16 elements (80B)
#define TILE_BYTES (128*LDT*2)         // 10240
#define STAGE_BYTES (4*TILE_BYTES)     // Ah, Al, Bh, Bl = 40960
#define GEMM_SMEM (2*STAGE_BYTES)      // 81920

template <bool RELU, bool EMITBF>
__global__ __launch_bounds__(256)
void gemm_tc(const bf16* __restrict__ Ah, const bf16* __restrict__ Al,
             const bf16* __restrict__ Bh, const bf16* __restrict__ Bl,
             const float* __restrict__ bias,
             const bf16* __restrict__ resh, const bf16* __restrict__ resl,
             float* __restrict__ C, bf16* __restrict__ Oh, bf16* __restrict__ Ol,
             int M, int N, int K) {
    extern __shared__ char smem[];
    uint32_t sb = smem_u32(smem);
    int tid = threadIdx.x, wid = tid >> 5, lane = tid & 31;
    int wm = wid >> 1, wn = wid & 1;
    int m0 = blockIdx.y * 128, n0 = blockIdx.x * 128;

    const bf16* Ahg = Ah + (size_t)m0 * K;
    const bf16* Alg = Al + (size_t)m0 * K;
    const bf16* Bhg = Bh + (size_t)n0 * K;
    const bf16* Blg = Bl + (size_t)n0 * K;

    const int nch = K >> 5;

    // loader: per chunk, each thread issues 8 cp.asyncs (2 per tile)
    auto load_chunk = [&](int c) {
        uint32_t st = sb + (uint32_t)(c & 1) * STAGE_BYTES;
        int koff = c * 32;
        #pragma unroll
        for (int i = 0; i < 2; i++) {
            int o = tid + i * 256;               // 0..511
            int row = o >> 2, seg = o & 3;
            size_t goff = (size_t)row * K + koff + seg * 8;
            uint32_t soff = (uint32_t)(row * LDT + seg * 8) * 2;
            cpa16(st + 0*TILE_BYTES + soff, Ahg + goff);
            cpa16(st + 1*TILE_BYTES + soff, Alg + goff);
            cpa16(st + 2*TILE_BYTES + soff, Bhg + goff);
            cpa16(st + 3*TILE_BYTES + soff, Blg + goff);
        }
        CP_COMMIT();
    };

    float acc[2][8][4];
    #pragma unroll
    for (int i = 0; i < 2; i++)
        #pragma unroll
        for (int j = 0; j < 8; j++)
            #pragma unroll
            for (int q = 0; q < 4; q++) acc[i][j][q] = 0.f;

    int a_r = ((lane >> 3) & 1) * 8 + (lane & 7);
    int a_c = (lane >> 4) * 8;
    int b_r = (lane >> 4) * 8 + (lane & 7);
    int b_c = ((lane >> 3) & 1) * 8;

    load_chunk(0);
    for (int c = 0; c < nch; c++) {
        if (c + 1 < nch) { load_chunk(c + 1); CP_WAIT1(); }
        else             { CP_WAIT0(); }
        __syncthreads();
        uint32_t stage = sb + (uint32_t)(c & 1) * STAGE_BYTES;
        #pragma unroll
        for (int k16 = 0; k16 < 32; k16 += 16) {
            uint32_t ah[2][4], al[2][4];
            #pragma unroll
            for (int mt = 0; mt < 2; mt++) {
                uint32_t ao = (uint32_t)((wm*32 + mt*16 + a_r) * LDT + k16 + a_c) * 2;
                ldm4(ah[mt], stage + 0*TILE_BYTES + ao);
                ldm4(al[mt], stage + 1*TILE_BYTES + ao);
            }
            #pragma unroll
            for (int nt = 0; nt < 4; nt++) {
                uint32_t bh[4], bl[4];
                uint32_t bo = (uint32_t)((wn*64 + nt*16 + b_r) * LDT + k16 + b_c) * 2;
                ldm4(bh, stage + 2*TILE_BYTES + bo);
                ldm4(bl, stage + 3*TILE_BYTES + bo);
                #pragma unroll
                for (int mt = 0; mt < 2; mt++) {
                    mma16816(acc[mt][2*nt+0], ah[mt], bh + 0);
                    mma16816(acc[mt][2*nt+0], al[mt], bh + 0);
                    mma16816(acc[mt][2*nt+0], ah[mt], bl + 0);
                    mma16816(acc[mt][2*nt+1], ah[mt], bh + 2);
                    mma16816(acc[mt][2*nt+1], al[mt], bh + 2);
                    mma16816(acc[mt][2*nt+1], ah[mt], bl + 2);
                }
            }
        }
        __syncthreads();
    }

    // ---- epilogue ----
    int trow = lane >> 2, tcol = (lane & 3) * 2;
    #pragma unroll
    for (int mt = 0; mt < 2; mt++) {
        #pragma unroll
        for (int rr = 0; rr < 2; rr++) {
            int row = m0 + wm*32 + mt*16 + rr*8 + trow;
            #pragma unroll
            for (int j = 0; j < 8; j++) {
                int col = n0 + wn*64 + j*8 + tcol;
                float v0 = acc[mt][j][rr*2+0];
                float v1 = acc[mt][j][rr*2+1];
                if (bias) { v0 += bias[col]; v1 += bias[col+1]; }
                if (RELU) { v0 = fmaxf(v0, 0.f); v1 = fmaxf(v1, 0.f); }
                if (resh) {
                    uint32_t rh = *(const uint32_t*)(resh + (size_t)row * N + col);
                    uint32_t rl = *(const uint32_t*)(resl + (size_t)row * N + col);
                    __nv_bfloat162 h2v = *(const __nv_bfloat162*)&rh;
                    __nv_bfloat162 l2v = *(const __nv_bfloat162*)&rl;
                    v0 += __bfloat162float(h2v.x) + __bfloat162float(l2v.x);
                    v1 += __bfloat162float(h2v.y) + __bfloat162float(l2v.y);
                }
                if (EMITBF) {
                    uint32_t hp, lp;
                    split2(v0, v1, hp, lp);
                    *(uint32_t*)(Oh + (size_t)row * N + col) = hp;
                    *(uint32_t*)(Ol + (size_t)row * N + col) = lp;
                } else {
                    float2 o2; o2.x = v0; o2.y = v1;
                    *(float2*)(C + (size_t)row * N + col) = o2;
                }
            }
        }
    }
}

// ============ Tensor-core causal flash attention ============================
// CTA: 128 q-rows of one (b,h); 8 warps x 16 rows. K-tile 64, cp.async 2-stage.
#define VST 72
#define ATILE_B (64*VST*2)                   // 9216
#define ASTAGE_B (4*ATILE_B)                 // 36864
#define ATTN_SMEM2 (2*ASTAGE_B)              // 73728

__global__ __launch_bounds__(256)
void attn_tc(const bf16* __restrict__ qh, const bf16* __restrict__ ql,
             bf16* __restrict__ oh, bf16* __restrict__ ol) {
    extern __shared__ char smem[];
    uint32_t sb = smem_u32(smem);
    int tid = threadIdx.x, w = tid >> 5, lane = tid & 31;
    int qb = (int)(gridDim.x - 1 - blockIdx.x);
    int b  = blockIdx.y >> 4, h = blockIdx.y & 15;
    int wrow  = qb * 128 + w * 16;
    int trow = lane >> 2, tc2 = (lane & 3) * 2;
    int gr0 = wrow + trow, gr1 = gr0 + 8;

    // Q fragments straight from gmem
    uint32_t Qh[4][4], Ql[4][4];
    {
        size_t r0 = ((size_t)b * TT + gr0) * D3 + h * 64;
        size_t r1 = ((size_t)b * TT + gr1) * D3 + h * 64;
        #pragma unroll
        for (int ks = 0; ks < 4; ks++) {
            int c0 = ks * 16 + tc2;
            Qh[ks][0] = *(const uint32_t*)(qh + r0 + c0);
            Qh[ks][1] = *(const uint32_t*)(qh + r1 + c0);
            Qh[ks][2] = *(const uint32_t*)(qh + r0 + c0 + 8);
            Qh[ks][3] = *(const uint32_t*)(qh + r1 + c0 + 8);
            Ql[ks][0] = *(const uint32_t*)(ql + r0 + c0);
            Ql[ks][1] = *(const uint32_t*)(ql + r1 + c0);
            Ql[ks][2] = *(const uint32_t*)(ql + r0 + c0 + 8);
            Ql[ks][3] = *(const uint32_t*)(ql + r1 + c0 + 8);
        }
    }

    float oacc[8][4];
    #pragma unroll
    for (int j = 0; j < 8; j++)
        #pragma unroll
        for (int q = 0; q < 4; q++) oacc[j][q] = 0.f;
    float m0 = -1e30f, m1 = -1e30f, l0 = 0.f, l1 = 0.f;

    const int nkt = 2 * qb + 2;
    size_t kcol = 1024 + h * 64;
    size_t vcol = 2048 + h * 64;

    auto load_tile = [&](int kt) {
        uint32_t st = sb + (uint32_t)(kt & 1) * ASTAGE_B;
        #pragma unroll
        for (int i = 0; i < 2; i++) {
            int o = tid + i * 256;              // 0..511
            int row = o >> 3, seg = o & 7;
            size_t gbase = ((size_t)b * TT + kt * 64 + row) * D3 + seg * 8;
            uint32_t soff = (uint32_t)(row * VST + seg * 8) * 2;
            cpa16(st + 0*ATILE_B + soff, qh + gbase + kcol);
            cpa16(st + 1*ATILE_B + soff, ql + gbase + kcol);
            cpa16(st + 2*ATILE_B + soff, qh + gbase + vcol);
            cpa16(st + 3*ATILE_B + soff, ql + gbase + vcol);
        }
        CP_COMMIT();
    };

    int kb_r = (lane >> 4) * 8 + (lane & 7);
    int kb_c = ((lane >> 3) & 1) * 8;
    int vb_r = ((lane >> 3) & 1) * 8 + (lane & 7);
    int vb_c = (lane >> 4) * 8;

    load_tile(0);
    for (int kt = 0; kt < nkt; kt++) {
        if (kt + 1 < nkt) { load_tile(kt + 1); CP_WAIT1(); }
        else              { CP_WAIT0(); }
        __syncthreads();
        uint32_t stage = sb + (uint32_t)(kt & 1) * ASTAGE_B;
        int kbkey = kt * 64;

        // ---- S = Q K^T (3-term) ----
        float sacc[8][4];
        #pragma unroll
        for (int j = 0; j < 8; j++)
            #pragma unroll
            for (int q = 0; q < 4; q++) sacc[j][q] = 0.f;
        #pragma unroll
        for (int ks = 0; ks < 4; ks++) {
            #pragma unroll
            for (int ng = 0; ng < 4; ng++) {
                uint32_t kh[4], kl[4];
                uint32_t ko = (uint32_t)((ng*16 + kb_r) * VST + ks*16 + kb_c) * 2;
                ldm4(kh, stage + 0*ATILE_B + ko);
                ldm4(kl, stage + 1*ATILE_B + ko);
                mma16816(sacc[2*ng+0], Qh[ks], kh + 0);
                mma16816(sacc[2*ng+0], Ql[ks], kh + 0);
                mma16816(sacc[2*ng+0], Qh[ks], kl + 0);
                mma16816(sacc[2*ng+1], Qh[ks], kh + 2);
                mma16816(sacc[2*ng+1], Ql[ks], kh + 2);
                mma16816(sacc[2*ng+1], Qh[ks], kl + 2);
            }
        }
        const float scale = 0.03125f;
        #pragma unroll
        for (int j = 0; j < 8; j++)
            #pragma unroll
            for (int q = 0; q < 4; q++) sacc[j][q] *= scale;
        if (kbkey + 63 > wrow) {
            #pragma unroll
            for (int j = 0; j < 8; j++) {
                int c0 = kbkey + j*8 + tc2;
                if (c0     > gr0) sacc[j][0] = -1e30f;
                if (c0 + 1 > gr0) sacc[j][1] = -1e30f;
                if (c0     > gr1) sacc[j][2] = -1e30f;
                if (c0 + 1 > gr1) sacc[j][3] = -1e30f;
            }
        }
        // ---- online softmax ----
        float mt0 = -1e30f, mt1 = -1e30f;
        #pragma unroll
        for (int j = 0; j < 8; j++) {
            mt0 = fmaxf(mt0, fmaxf(sacc[j][0], sacc[j][1]));
            mt1 = fmaxf(mt1, fmaxf(sacc[j][2], sacc[j][3]));
        }
        mt0 = fmaxf(mt0, __shfl_xor_sync(0xffffffffu, mt0, 1));
        mt0 = fmaxf(mt0, __shfl_xor_sync(0xffffffffu, mt0, 2));
        mt1 = fmaxf(mt1, __shfl_xor_sync(0xffffffffu, mt1, 1));
        mt1 = fmaxf(mt1, __shfl_xor_sync(0xffffffffu, mt1, 2));
        float mn0 = fmaxf(m0, mt0), mn1 = fmaxf(m1, mt1);
        float f0 = __expf(m0 - mn0), f1 = __expf(m1 - mn1);
        float rs0 = 0.f, rs1 = 0.f;
        #pragma unroll
        for (int j = 0; j < 8; j++) {
            sacc[j][0] = __expf(sacc[j][0] - mn0);
            sacc[j][1] = __expf(sacc[j][1] - mn0);
            sacc[j][2] = __expf(sacc[j][2] - mn1);
            sacc[j][3] = __expf(sacc[j][3] - mn1);
            rs0 += sacc[j][0] + sacc[j][1];
            rs1 += sacc[j][2] + sacc[j][3];
        }
        rs0 += __shfl_xor_sync(0xffffffffu, rs0, 1);
        rs0 += __shfl_xor_sync(0xffffffffu, rs0, 2);
        rs1 += __shfl_xor_sync(0xffffffffu, rs1, 1);
        rs1 += __shfl_xor_sync(0xffffffffu, rs1, 2);
        l0 = l0 * f0 + rs0;  l1 = l1 * f1 + rs1;
        m0 = mn0;  m1 = mn1;
        #pragma unroll
        for (int j = 0; j < 8; j++) {
            oacc[j][0] *= f0; oacc[j][1] *= f0;
            oacc[j][2] *= f1; oacc[j][3] *= f1;
        }
        // ---- O += P * V ----
        #pragma unroll
        for (int ks = 0; ks < 4; ks++) {
            uint32_t pfr[4];
            pfr[0] = pack_bf16(sacc[2*ks  ][0], sacc[2*ks  ][1]);
            pfr[1] = pack_bf16(sacc[2*ks  ][2], sacc[2*ks  ][3]);
            pfr[2] = pack_bf16(sacc[2*ks+1][0], sacc[2*ks+1][1]);
            pfr[3] = pack_bf16(sacc[2*ks+1][2], sacc[2*ks+1][3]);
            #pragma unroll
            for (int nd = 0; nd < 4; nd++) {
                uint32_t vh[4], vl[4];
                uint32_t vo = (uint32_t)((ks*16 + vb_r) * VST + nd*16 + vb_c) * 2;
                ldm4t(vh, stage + 2*ATILE_B + vo);
                ldm4t(vl, stage + 3*ATILE_B + vo);
                mma16816(oacc[2*nd+0], pfr, vh + 0);
                mma16816(oacc[2*nd+0], pfr, vl + 0);
                mma16816(oacc[2*nd+1], pfr, vh + 2);
                mma16816(oacc[2*nd+1], pfr, vl + 2);
            }
        }
        __syncthreads();
    }

    // ---- write O as bf16 pair ----
    float rl0 = 1.0f / l0, rl1 = 1.0f / l1;
    size_t ob0 = ((size_t)b * TT + gr0) * DD + h * 64;
    size_t ob1 = ((size_t)b * TT + gr1) * DD + h * 64;
    #pragma unroll
    for (int jd = 0; jd < 8; jd++) {
        uint32_t hp, lp;
        split2(oacc[jd][0] * rl0, oacc[jd][1] * rl0, hp, lp);
        *(uint32_t*)(oh + ob0 + jd*8 + tc2) = hp;
        *(uint32_t*)(ol + ob0 + jd*8 + tc2) = lp;
        split2(oacc[jd][2] * rl1, oacc[jd][3] * rl1, hp, lp);
        *(uint32_t*)(oh + ob1 + jd*8 + tc2) = hp;
        *(uint32_t*)(ol + ob1 + jd*8 + tc2) = lp;
    }
}

// ---------------- launch ------------------------------------------------------
extern "C" void kernel_launch(void* const* d_in, const int* in_sizes, int n_in,
                              void* d_out, int out_size) {
    const float* x   = (const float*)d_in[0];
    const float* Wq  = (const float*)d_in[1];
    const float* Wk  = (const float*)d_in[2];
    const float* Wv  = (const float*)d_in[3];
    const float* Wp  = (const float*)d_in[4];
    const float* bp  = (const float*)d_in[5];
    const float* W1  = (const float*)d_in[6];
    const float* b1  = (const float*)d_in[7];
    const float* W2  = (const float*)d_in[8];
    const float* b2  = (const float*)d_in[9];
    const float* g1  = (const float*)d_in[10];
    const float* be1 = (const float*)d_in[11];
    const float* g2  = (const float*)d_in[12];
    const float* be2 = (const float*)d_in[13];
    float* out = (float*)d_out;

    bf16 *hh, *hl, *oh, *ol, *x2h, *x2l, *h2h, *h2l, *mdh, *mdl, *qkvh, *qkvl;
    cudaGetSymbolAddress((void**)&hh,  g_hh);  cudaGetSymbolAddress((void**)&hl,  g_hl);
    cudaGetSymbolAddress((void**)&oh,  g_oh);  cudaGetSymbolAddress((void**)&ol,  g_ol);
    cudaGetSymbolAddress((void**)&x2h, g_x2h); cudaGetSymbolAddress((void**)&x2l, g_x2l);
    cudaGetSymbolAddress((void**)&h2h, g_h2h); cudaGetSymbolAddress((void**)&h2l, g_h2l);
    cudaGetSymbolAddress((void**)&mdh, g_mdh); cudaGetSymbolAddress((void**)&mdl, g_mdl);
    cudaGetSymbolAddress((void**)&qkvh, g_qkv_h); cudaGetSymbolAddress((void**)&qkvl, g_qkv_l);
    bf16 *Wqkv_h, *Wqkv_l, *Wp_h, *Wp_l, *W1_h, *W1_l, *W2_h, *W2_l;
    cudaGetSymbolAddress((void**)&Wqkv_h, g_Wqkv_h);
    cudaGetSymbolAddress((void**)&Wqkv_l, g_Wqkv_l);
    cudaGetSymbolAddress((void**)&Wp_h, g_Wp_h);
    cudaGetSymbolAddress((void**)&Wp_l, g_Wp_l);
    cudaGetSymbolAddress((void**)&W1_h, g_W1_h);
    cudaGetSymbolAddress((void**)&W1_l, g_W1_l);
    cudaGetSymbolAddress((void**)&W2_h, g_W2_h);
    cudaGetSymbolAddress((void**)&W2_l, g_W2_l);

    cudaFuncSetAttribute(attn_tc,
                         cudaFuncAttributeMaxDynamicSharedMemorySize, ATTN_SMEM2);
    cudaFuncSetAttribute(gemm_tc<false,true>,
                         cudaFuncAttributeMaxDynamicSharedMemorySize, GEMM_SMEM);
    cudaFuncSetAttribute(gemm_tc<true,true>,
                         cudaFuncAttributeMaxDynamicSharedMemorySize, GEMM_SMEM);
    cudaFuncSetAttribute(gemm_tc<false,false>,
                         cudaFuncAttributeMaxDynamicSharedMemorySize, GEMM_SMEM);

    dim3 tb(32, 8);
    prep_qkv<<<dim3(2, 32, 48), tb>>>(Wq, Wk, Wv, Wqkv_h, Wqkv_l);
    prep_tr<<<dim3(DD/32, DD/32), tb>>>(Wp, Wp_h, Wp_l, DD, DD);
    prep_tr<<<dim3(D4/32, DD/32), tb>>>(W1, W1_h, W1_l, DD, D4);
    prep_tr<<<dim3(DD/32, D4/32), tb>>>(W2, W2_h, W2_l, D4, DD);

    // LN1 (fp32 in, pair out)
    ln_kernel<false><<<MROWS, 256>>>(x, nullptr, nullptr, g1, be1, hh, hl);
    // QKV GEMM -> qkv pair
    gemm_tc<false,true><<<dim3(D3/128, MROWS/128), 256, GEMM_SMEM>>>(
        hh, hl, Wqkv_h, Wqkv_l, nullptr, nullptr, nullptr,
        nullptr, qkvh, qkvl, MROWS, D3, DD);
    // attention -> o pair
    attn_tc<<<dim3(TT/128, BB*HH), 256, ATTN_SMEM2>>>(qkvh, qkvl, oh, ol);
    // proj + bias + residual(h) -> x2 pair
    gemm_tc<false,true><<<dim3(DD/128, MROWS/128), 256, GEMM_SMEM>>>(
        oh, ol, Wp_h, Wp_l, bp, hh, hl,
        nullptr, x2h, x2l, MROWS, DD, DD);
    // LN2 (pair in, pair out)
    ln_kernel<true><<<MROWS, 256>>>(nullptr, x2h, x2l, g2, be2, h2h, h2l);
    // FFN1 + bias + relu -> mid pair
    gemm_tc<true,true><<<dim3(D4/128, MROWS/128), 256, GEMM_SMEM>>>(
        h2h, h2l, W1_h, W1_l, b1, nullptr, nullptr,
        nullptr, mdh, mdl, MROWS, D4, DD);
    // FFN2 + bias + residual(h2) -> fp32 out
    gemm_tc<false,false><<<dim3(DD/128, MROWS/128), 256, GEMM_SMEM>>>(
        mdh, mdl, W2_h, W2_l, b2, h2h, h2l,
        out, nullptr, nullptr, MROWS, DD, D4);
}

// round 6
// speedup vs baseline: 3.1628x; 1.1232x over previous
#include <cuda_runtime.h>
#include <cuda_bf16.h>
#include <cstdint>
#include <math.h>

// Problem constants
#define BB 4
#define TT 2048
#define DD 1024
#define HH 16
#define HS 64
#define MROWS (BB*TT)          // 8192
#define D3 (3*DD)              // 3072
#define D4 (4*DD)              // 4096

typedef __nv_bfloat16 bf16;

// ---------------- scratch (device globals; no allocs allowed) ----------------
__device__ bf16 g_hh [MROWS*DD], g_hl [MROWS*DD];     // LN1 out pair
__device__ bf16 g_oh [MROWS*DD], g_ol [MROWS*DD];     // attention out pair
__device__ bf16 g_x2h[MROWS*DD], g_x2l[MROWS*DD];     // h + proj pair
__device__ bf16 g_h2h[MROWS*DD], g_h2l[MROWS*DD];     // LN2 out pair
__device__ bf16 g_mdh[MROWS*D4], g_mdl[MROWS*D4];     // FFN hidden pair
__device__ bf16 g_qkv_h[MROWS*D3], g_qkv_l[MROWS*D3]; // qkv pair
// bf16 hi/lo weights, [N][K] layout
__device__ bf16 g_Wqkv_h[D3*DD], g_Wqkv_l[D3*DD];
__device__ bf16 g_Wp_h [DD*DD], g_Wp_l [DD*DD];
__device__ bf16 g_W1_h [D4*DD], g_W1_l [D4*DD];
__device__ bf16 g_W2_h [DD*D4], g_W2_l [DD*D4];

// ======================= small PTX helpers ===================================
__device__ __forceinline__ uint32_t smem_u32(const void* p) {
    uint32_t a;
    asm("{ .reg .u64 t; cvta.to.shared.u64 t, %1; cvt.u32.u64 %0, t; }" : "=r"(a) : "l"(p));
    return a;
}
__device__ __forceinline__ void ldm4(uint32_t* r, uint32_t addr) {
    asm volatile("ldmatrix.sync.aligned.m8n8.x4.shared.b16 {%0,%1,%2,%3}, [%4];"
        : "=r"(r[0]), "=r"(r[1]), "=r"(r[2]), "=r"(r[3]) : "r"(addr));
}
__device__ __forceinline__ void ldm4t(uint32_t* r, uint32_t addr) {
    asm volatile("ldmatrix.sync.aligned.m8n8.x4.trans.shared.b16 {%0,%1,%2,%3}, [%4];"
        : "=r"(r[0]), "=r"(r[1]), "=r"(r[2]), "=r"(r[3]) : "r"(addr));
}
__device__ __forceinline__ void mma16816(float* d, const uint32_t* a, const uint32_t* b) {
    asm volatile("mma.sync.aligned.m16n8k16.row.col.f32.bf16.bf16.f32 "
        "{%0,%1,%2,%3}, {%4,%5,%6,%7}, {%8,%9}, {%0,%1,%2,%3};"
        : "+f"(d[0]), "+f"(d[1]), "+f"(d[2]), "+f"(d[3])
        : "r"(a[0]), "r"(a[1]), "r"(a[2]), "r"(a[3]), "r"(b[0]), "r"(b[1]));
}
__device__ __forceinline__ uint32_t pack_bf16(float a, float b) {
    bf16 x = __float2bfloat16(a), y = __float2bfloat16(b);
    return ((uint32_t)__bfloat16_as_ushort(y) << 16) | __bfloat16_as_ushort(x);
}
__device__ __forceinline__ void split2(float a, float b, uint32_t& hp, uint32_t& lp) {
    bf16 h0 = __float2bfloat16(a), h1 = __float2bfloat16(b);
    hp = ((uint32_t)__bfloat16_as_ushort(h1) << 16) | __bfloat16_as_ushort(h0);
    lp = pack_bf16(a - __bfloat162float(h0), b - __bfloat162float(h1));
}
__device__ __forceinline__ void cpa16(uint32_t dst, const void* src) {
    asm volatile("cp.async.cg.shared.global [%0], [%1], 16;" :: "r"(dst), "l"(src));
}
#define CP_COMMIT() asm volatile("cp.async.commit_group;" ::: "memory")
#define CP_WAIT1()  asm volatile("cp.async.wait_group 1;" ::: "memory")
#define CP_WAIT0()  asm volatile("cp.async.wait_group 0;" ::: "memory")

// ======== weight prep: transpose W[K][N] -> out[N][K] bf16 hi/lo =============
__global__ void prep_tr(const float* __restrict__ W,
                        bf16* __restrict__ oh, bf16* __restrict__ ol, int K, int N) {
    __shared__ float ts[32][33];
    int n0 = blockIdx.x * 32, k0 = blockIdx.y * 32;
    int tx = threadIdx.x, ty = threadIdx.y;     // (32,8)
    #pragma unroll
    for (int i = 0; i < 4; i++)
        ts[ty + 8*i][tx] = W[(size_t)(k0 + ty + 8*i) * N + n0 + tx];
    __syncthreads();
    #pragma unroll
    for (int i = 0; i < 4; i++) {
        float v = ts[tx][ty + 8*i];
        size_t o = (size_t)(n0 + ty + 8*i) * K + k0 + tx;
        bf16 h = __float2bfloat16(v);
        oh[o] = h;
        ol[o] = __float2bfloat16(v - __bfloat162float(h));
    }
}

// QKV weights: Wq/Wk/Wv [H][D][HS] -> out[n=(sec,h,hs)][k=d] bf16 hi/lo
__global__ void prep_qkv(const float* __restrict__ Wq, const float* __restrict__ Wk,
                         const float* __restrict__ Wv,
                         bf16* __restrict__ oh, bf16* __restrict__ ol) {
    __shared__ float ts[32][33];
    int hs0 = blockIdx.x * 32;
    int d0  = blockIdx.y * 32;
    int z   = blockIdx.z;
    int sec = z >> 4, hh = z & 15;
    const float* W = (sec == 0) ? Wq : (sec == 1) ? Wk : Wv;
    int tx = threadIdx.x, ty = threadIdx.y;
    #pragma unroll
    for (int i = 0; i < 4; i++)
        ts[ty + 8*i][tx] = W[(size_t)hh * (DD*HS) + (size_t)(d0 + ty + 8*i) * HS + hs0 + tx];
    __syncthreads();
    #pragma unroll
    for (int i = 0; i < 4; i++) {
        float v = ts[tx][ty + 8*i];
        int n = sec * 1024 + hh * 64 + hs0 + ty + 8*i;
        size_t o = (size_t)n * DD + d0 + tx;
        bf16 h = __float2bfloat16(v);
        oh[o] = h;
        ol[o] = __float2bfloat16(v - __bfloat162float(h));
    }
}

// ---------------- LayerNorm: fp32 or pair input -> pair output ---------------
template <bool PAIRIN>
__global__ void ln_kernel(const float* __restrict__ x,
                          const bf16* __restrict__ xh, const bf16* __restrict__ xl,
                          const float* __restrict__ g, const float* __restrict__ b,
                          bf16* __restrict__ yh, bf16* __restrict__ yl) {
    int row = blockIdx.x;
    int tid = threadIdx.x;
    float4 v;
    if (PAIRIN) {
        const uint2 hv = *(const uint2*)(xh + (size_t)row * DD + tid * 4);
        const uint2 lv = *(const uint2*)(xl + (size_t)row * DD + tid * 4);
        __nv_bfloat162 h0 = *(const __nv_bfloat162*)&hv.x;
        __nv_bfloat162 h1 = *(const __nv_bfloat162*)&hv.y;
        __nv_bfloat162 l0 = *(const __nv_bfloat162*)&lv.x;
        __nv_bfloat162 l1 = *(const __nv_bfloat162*)&lv.y;
        v.x = __bfloat162float(h0.x) + __bfloat162float(l0.x);
        v.y = __bfloat162float(h0.y) + __bfloat162float(l0.y);
        v.z = __bfloat162float(h1.x) + __bfloat162float(l1.x);
        v.w = __bfloat162float(h1.y) + __bfloat162float(l1.y);
    } else {
        v = *(const float4*)(x + (size_t)row * DD + tid * 4);
    }
    float s  = v.x + v.y + v.z + v.w;
    float sq = v.x*v.x + v.y*v.y + v.z*v.z + v.w*v.w;
    #pragma unroll
    for (int o = 16; o > 0; o >>= 1) {
        s  += __shfl_xor_sync(0xffffffffu, s,  o);
        sq += __shfl_xor_sync(0xffffffffu, sq, o);
    }
    __shared__ float ws[8], wq[8];
    int wid = tid >> 5, lid = tid & 31;
    if (lid == 0) { ws[wid] = s; wq[wid] = sq; }
    __syncthreads();
    if (wid == 0) {
        float a = (lid < 8) ? ws[lid] : 0.f;
        float c = (lid < 8) ? wq[lid] : 0.f;
        #pragma unroll
        for (int o = 4; o > 0; o >>= 1) {
            a += __shfl_xor_sync(0xffffffffu, a, o);
            c += __shfl_xor_sync(0xffffffffu, c, o);
        }
        if (lid == 0) { ws[0] = a; wq[0] = c; }
    }
    __syncthreads();
    float mu  = ws[0] * (1.0f / DD);
    float var = wq[0] * (1.0f / DD) - mu * mu;
    float inv = rsqrtf(var + 1e-5f);
    const float4 gg = *(const float4*)(g + tid * 4);
    const float4 bb = *(const float4*)(b + tid * 4);
    float o0 = (v.x - mu) * inv * gg.x + bb.x;
    float o1 = (v.y - mu) * inv * gg.y + bb.y;
    float o2 = (v.z - mu) * inv * gg.z + bb.z;
    float o3 = (v.w - mu) * inv * gg.w + bb.w;
    uint2 hp, lp;
    split2(o0, o1, hp.x, lp.x);
    split2(o2, o3, hp.y, lp.y);
    *(uint2*)(yh + (size_t)row * DD + tid * 4) = hp;
    *(uint2*)(yl + (size_t)row * DD + tid * 4) = lp;
}

// ============ mma.sync GEMM: C[M,N] = (Ah+Al)[M,K] @ (Bh+Bl)[N,K]^T ==========
// 3-term split-bf16 fp32 accum. cp.async 2-stage pipeline. 2 CTAs/SM.
#define LDT 40                         // smem row stride in bf16 elements (80B)
#define TILE_BYTES (128*LDT*2)         // 10240
#define STAGE_BYTES (4*TILE_BYTES)     // Ah, Al, Bh, Bl = 40960
#define GEMM_SMEM (2*STAGE_BYTES)      // 81920

template <bool RELU, bool EMITBF>
__global__ __launch_bounds__(256, 2)
void gemm_tc(const bf16* __restrict__ Ah, const bf16* __restrict__ Al,
             const bf16* __restrict__ Bh, const bf16* __restrict__ Bl,
             const float* __restrict__ bias,
             const bf16* __restrict__ resh, const bf16* __restrict__ resl,
             float* __restrict__ C, bf16* __restrict__ Oh, bf16* __restrict__ Ol,
             int M, int N, int K) {
    extern __shared__ char smem[];
    uint32_t sb = smem_u32(smem);
    int tid = threadIdx.x, wid = tid >> 5, lane = tid & 31;
    int wm = wid >> 1, wn = wid & 1;
    int m0 = blockIdx.y * 128, n0 = blockIdx.x * 128;

    // per-thread gmem cursors (advance by +32 elements per chunk)
    int lrow = tid >> 2, lseg = (tid & 3) * 8;       // 4 threads/row, 8 elems each
    const bf16* pAh = Ah + (size_t)(m0 + lrow) * K + lseg;
    const bf16* pAl = Al + (size_t)(m0 + lrow) * K + lseg;
    const bf16* pBh = Bh + (size_t)(n0 + lrow) * K + lseg;
    const bf16* pBl = Bl + (size_t)(n0 + lrow) * K + lseg;
    // two smem offsets per tile (rows lrow and lrow+64)
    uint32_t so0 = (uint32_t)(lrow * LDT + lseg) * 2;
    uint32_t so1 = (uint32_t)((lrow + 64) * LDT + lseg) * 2;
    const size_t half = (size_t)64 * K;

    const int nch = K >> 5;

    auto load_chunk = [&](int c) {
        uint32_t st = sb + (uint32_t)(c & 1) * STAGE_BYTES;
        int koff = c * 32;
        cpa16(st + 0*TILE_BYTES + so0, pAh + koff);
        cpa16(st + 0*TILE_BYTES + so1, pAh + half + koff);
        cpa16(st + 1*TILE_BYTES + so0, pAl + koff);
        cpa16(st + 1*TILE_BYTES + so1, pAl + half + koff);
        cpa16(st + 2*TILE_BYTES + so0, pBh + koff);
        cpa16(st + 2*TILE_BYTES + so1, pBh + half + koff);
        cpa16(st + 3*TILE_BYTES + so0, pBl + koff);
        cpa16(st + 3*TILE_BYTES + so1, pBl + half + koff);
        CP_COMMIT();
    };

    float acc[2][8][4];
    #pragma unroll
    for (int i = 0; i < 2; i++)
        #pragma unroll
        for (int j = 0; j < 8; j++)
            #pragma unroll
            for (int q = 0; q < 4; q++) acc[i][j][q] = 0.f;

    int a_r = ((lane >> 3) & 1) * 8 + (lane & 7);
    int a_c = (lane >> 4) * 8;
    int b_r = (lane >> 4) * 8 + (lane & 7);
    int b_c = ((lane >> 3) & 1) * 8;

    load_chunk(0);
    for (int c = 0; c < nch; c++) {
        if (c + 1 < nch) { load_chunk(c + 1); CP_WAIT1(); }
        else             { CP_WAIT0(); }
        __syncthreads();
        uint32_t stage = sb + (uint32_t)(c & 1) * STAGE_BYTES;
        #pragma unroll
        for (int k16 = 0; k16 < 32; k16 += 16) {
            uint32_t ah[2][4], al[2][4];
            #pragma unroll
            for (int mt = 0; mt < 2; mt++) {
                uint32_t ao = (uint32_t)((wm*32 + mt*16 + a_r) * LDT + k16 + a_c) * 2;
                ldm4(ah[mt], stage + 0*TILE_BYTES + ao);
                ldm4(al[mt], stage + 1*TILE_BYTES + ao);
            }
            #pragma unroll
            for (int nt = 0; nt < 4; nt++) {
                uint32_t bh[4], bl[4];
                uint32_t bo = (uint32_t)((wn*64 + nt*16 + b_r) * LDT + k16 + b_c) * 2;
                ldm4(bh, stage + 2*TILE_BYTES + bo);
                ldm4(bl, stage + 3*TILE_BYTES + bo);
                #pragma unroll
                for (int mt = 0; mt < 2; mt++) {
                    mma16816(acc[mt][2*nt+0], ah[mt], bh + 0);
                    mma16816(acc[mt][2*nt+0], al[mt], bh + 0);
                    mma16816(acc[mt][2*nt+0], ah[mt], bl + 0);
                    mma16816(acc[mt][2*nt+1], ah[mt], bh + 2);
                    mma16816(acc[mt][2*nt+1], al[mt], bh + 2);
                    mma16816(acc[mt][2*nt+1], ah[mt], bl + 2);
                }
            }
        }
        __syncthreads();
    }

    // ---- epilogue ----
    int trow = lane >> 2, tcol = (lane & 3) * 2;
    #pragma unroll
    for (int mt = 0; mt < 2; mt++) {
        #pragma unroll
        for (int rr = 0; rr < 2; rr++) {
            int row = m0 + wm*32 + mt*16 + rr*8 + trow;
            #pragma unroll
            for (int j = 0; j < 8; j++) {
                int col = n0 + wn*64 + j*8 + tcol;
                float v0 = acc[mt][j][rr*2+0];
                float v1 = acc[mt][j][rr*2+1];
                if (bias) { v0 += bias[col]; v1 += bias[col+1]; }
                if (RELU) { v0 = fmaxf(v0, 0.f); v1 = fmaxf(v1, 0.f); }
                if (resh) {
                    uint32_t rh = *(const uint32_t*)(resh + (size_t)row * N + col);
                    uint32_t rl = *(const uint32_t*)(resl + (size_t)row * N + col);
                    __nv_bfloat162 h2v = *(const __nv_bfloat162*)&rh;
                    __nv_bfloat162 l2v = *(const __nv_bfloat162*)&rl;
                    v0 += __bfloat162float(h2v.x) + __bfloat162float(l2v.x);
                    v1 += __bfloat162float(h2v.y) + __bfloat162float(l2v.y);
                }
                if (EMITBF) {
                    uint32_t hp, lp;
                    split2(v0, v1, hp, lp);
                    *(uint32_t*)(Oh + (size_t)row * N + col) = hp;
                    *(uint32_t*)(Ol + (size_t)row * N + col) = lp;
                } else {
                    float2 o2; o2.x = v0; o2.y = v1;
                    *(float2*)(C + (size_t)row * N + col) = o2;
                }
            }
        }
    }
}

// ============ Tensor-core causal flash attention ============================
// CTA: 128 q-rows of one (b,h); 8 warps x 16 rows. K-tile 64, cp.async 2-stage.
#define VST 72
#define ATILE_B (64*VST*2)                   // 9216
#define ASTAGE_B (4*ATILE_B)                 // 36864
#define ATTN_SMEM2 (2*ASTAGE_B)              // 73728

__global__ __launch_bounds__(256)
void attn_tc(const bf16* __restrict__ qh, const bf16* __restrict__ ql,
             bf16* __restrict__ oh, bf16* __restrict__ ol) {
    extern __shared__ char smem[];
    uint32_t sb = smem_u32(smem);
    int tid = threadIdx.x, w = tid >> 5, lane = tid & 31;
    int qb = (int)(gridDim.x - 1 - blockIdx.x);
    int b  = blockIdx.y >> 4, h = blockIdx.y & 15;
    int wrow  = qb * 128 + w * 16;
    int trow = lane >> 2, tc2 = (lane & 3) * 2;
    int gr0 = wrow + trow, gr1 = gr0 + 8;

    // Q fragments straight from gmem
    uint32_t Qh[4][4], Ql[4][4];
    {
        size_t r0 = ((size_t)b * TT + gr0) * D3 + h * 64;
        size_t r1 = ((size_t)b * TT + gr1) * D3 + h * 64;
        #pragma unroll
        for (int ks = 0; ks < 4; ks++) {
            int c0 = ks * 16 + tc2;
            Qh[ks][0] = *(const uint32_t*)(qh + r0 + c0);
            Qh[ks][1] = *(const uint32_t*)(qh + r1 + c0);
            Qh[ks][2] = *(const uint32_t*)(qh + r0 + c0 + 8);
            Qh[ks][3] = *(const uint32_t*)(qh + r1 + c0 + 8);
            Ql[ks][0] = *(const uint32_t*)(ql + r0 + c0);
            Ql[ks][1] = *(const uint32_t*)(ql + r1 + c0);
            Ql[ks][2] = *(const uint32_t*)(ql + r0 + c0 + 8);
            Ql[ks][3] = *(const uint32_t*)(ql + r1 + c0 + 8);
        }
    }

    float oacc[8][4];
    #pragma unroll
    for (int j = 0; j < 8; j++)
        #pragma unroll
        for (int q = 0; q < 4; q++) oacc[j][q] = 0.f;
    float m0 = -1e30f, m1 = -1e30f, l0 = 0.f, l1 = 0.f;

    const int nkt = 2 * qb + 2;
    size_t kcol = 1024 + h * 64;
    size_t vcol = 2048 + h * 64;

    auto load_tile = [&](int kt) {
        uint32_t st = sb + (uint32_t)(kt & 1) * ASTAGE_B;
        #pragma unroll
        for (int i = 0; i < 2; i++) {
            int o = tid + i * 256;              // 0..511
            int row = o >> 3, seg = o & 7;
            size_t gbase = ((size_t)b * TT + kt * 64 + row) * D3 + seg * 8;
            uint32_t soff = (uint32_t)(row * VST + seg * 8) * 2;
            cpa16(st + 0*ATILE_B + soff, qh + gbase + kcol);
            cpa16(st + 1*ATILE_B + soff, ql + gbase + kcol);
            cpa16(st + 2*ATILE_B + soff, qh + gbase + vcol);
            cpa16(st + 3*ATILE_B + soff, ql + gbase + vcol);
        }
        CP_COMMIT();
    };

    int kb_r = (lane >> 4) * 8 + (lane & 7);
    int kb_c = ((lane >> 3) & 1) * 8;
    int vb_r = ((lane >> 3) & 1) * 8 + (lane & 7);
    int vb_c = (lane >> 4) * 8;

    load_tile(0);
    for (int kt = 0; kt < nkt; kt++) {
        if (kt + 1 < nkt) { load_tile(kt + 1); CP_WAIT1(); }
        else              { CP_WAIT0(); }
        __syncthreads();
        uint32_t stage = sb + (uint32_t)(kt & 1) * ASTAGE_B;
        int kbkey = kt * 64;

        // ---- S = Q K^T (3-term) ----
        float sacc[8][4];
        #pragma unroll
        for (int j = 0; j < 8; j++)
            #pragma unroll
            for (int q = 0; q < 4; q++) sacc[j][q] = 0.f;
        #pragma unroll
        for (int ks = 0; ks < 4; ks++) {
            #pragma unroll
            for (int ng = 0; ng < 4; ng++) {
                uint32_t kh[4], kl[4];
                uint32_t ko = (uint32_t)((ng*16 + kb_r) * VST + ks*16 + kb_c) * 2;
                ldm4(kh, stage + 0*ATILE_B + ko);
                ldm4(kl, stage + 1*ATILE_B + ko);
                mma16816(sacc[2*ng+0], Qh[ks], kh + 0);
                mma16816(sacc[2*ng+0], Ql[ks], kh + 0);
                mma16816(sacc[2*ng+0], Qh[ks], kl + 0);
                mma16816(sacc[2*ng+1], Qh[ks], kh + 2);
                mma16816(sacc[2*ng+1], Ql[ks], kh + 2);
                mma16816(sacc[2*ng+1], Qh[ks], kl + 2);
            }
        }
        const float scale = 0.03125f;
        #pragma unroll
        for (int j = 0; j < 8; j++)
            #pragma unroll
            for (int q = 0; q < 4; q++) sacc[j][q] *= scale;
        if (kbkey + 63 > wrow) {
            #pragma unroll
            for (int j = 0; j < 8; j++) {
                int c0 = kbkey + j*8 + tc2;
                if (c0     > gr0) sacc[j][0] = -1e30f;
                if (c0 + 1 > gr0) sacc[j][1] = -1e30f;
                if (c0     > gr1) sacc[j][2] = -1e30f;
                if (c0 + 1 > gr1) sacc[j][3] = -1e30f;
            }
        }
        // ---- online softmax ----
        float mt0 = -1e30f, mt1 = -1e30f;
        #pragma unroll
        for (int j = 0; j < 8; j++) {
            mt0 = fmaxf(mt0, fmaxf(sacc[j][0], sacc[j][1]));
            mt1 = fmaxf(mt1, fmaxf(sacc[j][2], sacc[j][3]));
        }
        mt0 = fmaxf(mt0, __shfl_xor_sync(0xffffffffu, mt0, 1));
        mt0 = fmaxf(mt0, __shfl_xor_sync(0xffffffffu, mt0, 2));
        mt1 = fmaxf(mt1, __shfl_xor_sync(0xffffffffu, mt1, 1));
        mt1 = fmaxf(mt1, __shfl_xor_sync(0xffffffffu, mt1, 2));
        float mn0 = fmaxf(m0, mt0), mn1 = fmaxf(m1, mt1);
        float f0 = __expf(m0 - mn0), f1 = __expf(m1 - mn1);
        float rs0 = 0.f, rs1 = 0.f;
        #pragma unroll
        for (int j = 0; j < 8; j++) {
            sacc[j][0] = __expf(sacc[j][0] - mn0);
            sacc[j][1] = __expf(sacc[j][1] - mn0);
            sacc[j][2] = __expf(sacc[j][2] - mn1);
            sacc[j][3] = __expf(sacc[j][3] - mn1);
            rs0 += sacc[j][0] + sacc[j][1];
            rs1 += sacc[j][2] + sacc[j][3];
        }
        rs0 += __shfl_xor_sync(0xffffffffu, rs0, 1);
        rs0 += __shfl_xor_sync(0xffffffffu, rs0, 2);
        rs1 += __shfl_xor_sync(0xffffffffu, rs1, 1);
        rs1 += __shfl_xor_sync(0xffffffffu, rs1, 2);
        l0 = l0 * f0 + rs0;  l1 = l1 * f1 + rs1;
        m0 = mn0;  m1 = mn1;
        #pragma unroll
        for (int j = 0; j < 8; j++) {
            oacc[j][0] *= f0; oacc[j][1] *= f0;
            oacc[j][2] *= f1; oacc[j][3] *= f1;
        }
        // ---- O += P * V ----
        #pragma unroll
        for (int ks = 0; ks < 4; ks++) {
            uint32_t pfr[4];
            pfr[0] = pack_bf16(sacc[2*ks  ][0], sacc[2*ks  ][1]);
            pfr[1] = pack_bf16(sacc[2*ks  ][2], sacc[2*ks  ][3]);
            pfr[2] = pack_bf16(sacc[2*ks+1][0], sacc[2*ks+1][1]);
            pfr[3] = pack_bf16(sacc[2*ks+1][2], sacc[2*ks+1][3]);
            #pragma unroll
            for (int nd = 0; nd < 4; nd++) {
                uint32_t vh[4], vl[4];
                uint32_t vo = (uint32_t)((ks*16 + vb_r) * VST + nd*16 + vb_c) * 2;
                ldm4t(vh, stage + 2*ATILE_B + vo);
                ldm4t(vl, stage + 3*ATILE_B + vo);
                mma16816(oacc[2*nd+0], pfr, vh + 0);
                mma16816(oacc[2*nd+0], pfr, vl + 0);
                mma16816(oacc[2*nd+1], pfr, vh + 2);
                mma16816(oacc[2*nd+1], pfr, vl + 2);
            }
        }
        __syncthreads();
    }

    // ---- write O as bf16 pair ----
    float rl0 = 1.0f / l0, rl1 = 1.0f / l1;
    size_t ob0 = ((size_t)b * TT + gr0) * DD + h * 64;
    size_t ob1 = ((size_t)b * TT + gr1) * DD + h * 64;
    #pragma unroll
    for (int jd = 0; jd < 8; jd++) {
        uint32_t hp, lp;
        split2(oacc[jd][0] * rl0, oacc[jd][1] * rl0, hp, lp);
        *(uint32_t*)(oh + ob0 + jd*8 + tc2) = hp;
        *(uint32_t*)(ol + ob0 + jd*8 + tc2) = lp;
        split2(oacc[jd][2] * rl1, oacc[jd][3] * rl1, hp, lp);
        *(uint32_t*)(oh + ob1 + jd*8 + tc2) = hp;
        *(uint32_t*)(ol + ob1 + jd*8 + tc2) = lp;
    }
}

// ---------------- launch ------------------------------------------------------
extern "C" void kernel_launch(void* const* d_in, const int* in_sizes, int n_in,
                              void* d_out, int out_size) {
    const float* x   = (const float*)d_in[0];
    const float* Wq  = (const float*)d_in[1];
    const float* Wk  = (const float*)d_in[2];
    const float* Wv  = (const float*)d_in[3];
    const float* Wp  = (const float*)d_in[4];
    const float* bp  = (const float*)d_in[5];
    const float* W1  = (const float*)d_in[6];
    const float* b1  = (const float*)d_in[7];
    const float* W2  = (const float*)d_in[8];
    const float* b2  = (const float*)d_in[9];
    const float* g1  = (const float*)d_in[10];
    const float* be1 = (const float*)d_in[11];
    const float* g2  = (const float*)d_in[12];
    const float* be2 = (const float*)d_in[13];
    float* out = (float*)d_out;

    bf16 *hh, *hl, *oh, *ol, *x2h, *x2l, *h2h, *h2l, *mdh, *mdl, *qkvh, *qkvl;
    cudaGetSymbolAddress((void**)&hh,  g_hh);  cudaGetSymbolAddress((void**)&hl,  g_hl);
    cudaGetSymbolAddress((void**)&oh,  g_oh);  cudaGetSymbolAddress((void**)&ol,  g_ol);
    cudaGetSymbolAddress((void**)&x2h, g_x2h); cudaGetSymbolAddress((void**)&x2l, g_x2l);
    cudaGetSymbolAddress((void**)&h2h, g_h2h); cudaGetSymbolAddress((void**)&h2l, g_h2l);
    cudaGetSymbolAddress((void**)&mdh, g_mdh); cudaGetSymbolAddress((void**)&mdl, g_mdl);
    cudaGetSymbolAddress((void**)&qkvh, g_qkv_h); cudaGetSymbolAddress((void**)&qkvl, g_qkv_l);
    bf16 *Wqkv_h, *Wqkv_l, *Wp_h, *Wp_l, *W1_h, *W1_l, *W2_h, *W2_l;
    cudaGetSymbolAddress((void**)&Wqkv_h, g_Wqkv_h);
    cudaGetSymbolAddress((void**)&Wqkv_l, g_Wqkv_l);
    cudaGetSymbolAddress((void**)&Wp_h, g_Wp_h);
    cudaGetSymbolAddress((void**)&Wp_l, g_Wp_l);
    cudaGetSymbolAddress((void**)&W1_h, g_W1_h);
    cudaGetSymbolAddress((void**)&W1_l, g_W1_l);
    cudaGetSymbolAddress((void**)&W2_h, g_W2_h);
    cudaGetSymbolAddress((void**)&W2_l, g_W2_l);

    cudaFuncSetAttribute(attn_tc,
                         cudaFuncAttributeMaxDynamicSharedMemorySize, ATTN_SMEM2);
    cudaFuncSetAttribute(gemm_tc<false,true>,
                         cudaFuncAttributeMaxDynamicSharedMemorySize, GEMM_SMEM);
    cudaFuncSetAttribute(gemm_tc<true,true>,
                         cudaFuncAttributeMaxDynamicSharedMemorySize, GEMM_SMEM);
    cudaFuncSetAttribute(gemm_tc<false,false>,
                         cudaFuncAttributeMaxDynamicSharedMemorySize, GEMM_SMEM);

    dim3 tb(32, 8);
    prep_qkv<<<dim3(2, 32, 48), tb>>>(Wq, Wk, Wv, Wqkv_h, Wqkv_l);
    prep_tr<<<dim3(DD/32, DD/32), tb>>>(Wp, Wp_h, Wp_l, DD, DD);
    prep_tr<<<dim3(D4/32, DD/32), tb>>>(W1, W1_h, W1_l, DD, D4);
    prep_tr<<<dim3(DD/32, D4/32), tb>>>(W2, W2_h, W2_l, D4, DD);

    // LN1 (fp32 in, pair out)
    ln_kernel<false><<<MROWS, 256>>>(x, nullptr, nullptr, g1, be1, hh, hl);
    // QKV GEMM -> qkv pair
    gemm_tc<false,true><<<dim3(D3/128, MROWS/128), 256, GEMM_SMEM>>>(
        hh, hl, Wqkv_h, Wqkv_l, nullptr, nullptr, nullptr,
        nullptr, qkvh, qkvl, MROWS, D3, DD);
    // attention -> o pair
    attn_tc<<<dim3(TT/128, BB*HH), 256, ATTN_SMEM2>>>(qkvh, qkvl, oh, ol);
    // proj + bias + residual(h) -> x2 pair
    gemm_tc<false,true><<<dim3(DD/128, MROWS/128), 256, GEMM_SMEM>>>(
        oh, ol, Wp_h, Wp_l, bp, hh, hl,
        nullptr, x2h, x2l, MROWS, DD, DD);
    // LN2 (pair in, pair out)
    ln_kernel<true><<<MROWS, 256>>>(nullptr, x2h, x2l, g2, be2, h2h, h2l);
    // FFN1 + bias + relu -> mid pair
    gemm_tc<true,true><<<dim3(D4/128, MROWS/128), 256, GEMM_SMEM>>>(
        h2h, h2l, W1_h, W1_l, b1, nullptr, nullptr,
        nullptr, mdh, mdl, MROWS, D4, DD);
    // FFN2 + bias + residual(h2) -> fp32 out
    gemm_tc<false,false><<<dim3(DD/128, MROWS/128), 256, GEMM_SMEM>>>(
        mdh, mdl, W2_h, W2_l, b2, h2h, h2l,
        out, nullptr, nullptr, MROWS, DD, D4);
}